// round 13
// baseline (speedup 1.0000x reference)
#include <cuda_runtime.h>
#include <cuda_bf16.h>
#include <math.h>
#include <stdint.h>

#define Bn 4
#define Sn 2048
#define Dn 1024
#define BSn (Bn*Sn)
#define KP 2048          // physical operand pitch: [hi | lo] segments
#define KTOT 48          // logical K chunks (3 * 1024 / 64)
#define NSPLIT 3         // GEMM1 split-K factor

// ---------------- scratch (static device arrays; no allocation allowed) -----
__device__ float  g_x[(size_t)BSn * Dn];             // layernormed context (fp32)
__device__ float  g_y[(size_t)BSn * Dn];             // x @ M  (fp32)
__device__ __nv_bfloat16 g_A2[(size_t)BSn * KP];     // [x_hi | x_lo]
__device__ __nv_bfloat16 g_B2[(size_t)Dn * KP];      // [M_hi | M_lo] (rows = output col b)
__device__ __nv_bfloat16 g_A1[(size_t)Dn * KP];      // [Wq_hi | Wq_lo]
__device__ __nv_bfloat16 g_B1[(size_t)Dn * KP];      // [Wk_hi | Wk_lo]
__device__ float  g_Mp[NSPLIT * (size_t)Dn * Dn];    // split-K partials of M
__device__ float  g_u[Dn];                 // Wq @ bk
__device__ float  g_v[Dn];                 // Wk @ bq
__device__ float  g_c;                     // bq . bk
__device__ float  g_xu[BSn], g_xv[BSn], g_dup[BSn], g_ddn[BSn];
__device__ float  g_rvup[BSn], g_rvdn[BSn], g_rvdiag[BSn];
__device__ unsigned char g_fm[BSn];        // fully-masked row flag
__device__ double g_P[BSn];

// ======================= helpers ============================================
__device__ __forceinline__ uint32_t smem_u32(const void* p) {
    uint32_t a;
    asm("{ .reg .u64 t; cvta.to.shared.u64 t, %1; cvt.u32.u64 %0, t; }" : "=r"(a) : "l"(p));
    return a;
}
__device__ __forceinline__ void cp_async16(uint32_t dst, const void* src) {
    asm volatile("cp.async.cg.shared.global [%0], [%1], 16;" :: "r"(dst), "l"(src) : "memory");
}
__device__ __forceinline__ void cp_commit() {
    asm volatile("cp.async.commit_group;" ::: "memory");
}
__device__ __forceinline__ void cp_wait1() {
    asm volatile("cp.async.wait_group 1;" ::: "memory");
}
__device__ __forceinline__ void ldm_x4(uint32_t* r, uint32_t addr) {
    asm volatile("ldmatrix.sync.aligned.m8n8.x4.shared.b16 {%0,%1,%2,%3}, [%4];"
        : "=r"(r[0]), "=r"(r[1]), "=r"(r[2]), "=r"(r[3]) : "r"(addr));
}
__device__ __forceinline__ void mma_bf16(float* c, const uint32_t* a, uint32_t b0, uint32_t b1) {
    asm volatile("mma.sync.aligned.m16n8k16.row.col.f32.bf16.bf16.f32 "
        "{%0,%1,%2,%3}, {%4,%5,%6,%7}, {%8,%9}, {%0,%1,%2,%3};"
        : "+f"(c[0]), "+f"(c[1]), "+f"(c[2]), "+f"(c[3])
        : "r"(a[0]), "r"(a[1]), "r"(a[2]), "r"(a[3]), "r"(b0), "r"(b1));
}

// ===================== HMMA bf16 GEMM =======================================
// Logical: C[M,N] = sum over 48 K-chunks of A'[.,g] * B'[.,g]^T where
//   A' chunk g maps to physical chunk (g<32 ? g : g-32) of [hi|lo] storage,
//   B' chunk g maps to physical chunk (g<16 ? g : g-16).
// This realizes the 3-term split product (xh*Mh + xl*Mh + xh*Ml) without
// storing duplicated segments.
// Template BN: 128 -> 128 threads (2x2 warps of 64x64, 2 CTAs/SM);
//              256 -> 256 threads (2x4 warps of 64x64, 1 CTA/SM, halves A
//              re-read traffic through L2).
// BM=128, BK=64, 3-stage cp.async pipeline.
// blockIdx.z = K-split; out to Cf + z*zstride.
template <int BN>
__global__ __launch_bounds__(BN == 128 ? 128 : 256, BN == 128 ? 2 : 1)
void gemm_mma(const __nv_bfloat16* __restrict__ A,
              const __nv_bfloat16* __restrict__ Bm,
              float* __restrict__ Cf,
              int c_pitch, size_t zstride, int kcn) {
    constexpr int NT = (BN == 128) ? 128 : 256;   // threads
    constexpr int WN = BN / 64;                    // warps along n
    constexpr int ASIZE = 128 * 128;               // 16 KB (128 rows x 128B)
    constexpr int BSIZE = BN * 128;                // BN rows x 128B
    constexpr int STAGE = ASIZE + BSIZE;
    constexpr int RPI = NT / 8;                    // rows loaded per iter
    extern __shared__ char smem[];
    uint32_t sbase = smem_u32(smem);
    int t = threadIdx.x, wid = t >> 5, lane = t & 31;
    int wm = wid & 1, wn = wid >> 1;               // 2 x WN warp grid, 64x64 tiles
    int rowBlk = blockIdx.y * 128;
    int colBlk = blockIdx.x * BN;
    int z = blockIdx.z;
    int zbase = z * kcn;

    const __nv_bfloat16* Ab = A + (size_t)rowBlk * KP;
    const __nv_bfloat16* Bb = Bm + (size_t)colBlk * KP;

    int lr = t >> 3, lj = t & 7;                   // NT thr -> NT/8 rows x 8 chunks
    uint32_t sw = ((uint32_t)(lj ^ (lr & 7))) << 4;

    auto load = [&](int c, int s) {
        int g = zbase + c;
        int ga = (g < 32 ? g : g - 32) * 64;       // A physical column offset
        int gb = (g < 16 ? g : g - 16) * 64;       // B physical column offset
        uint32_t sa = sbase + (uint32_t)s * STAGE;
        #pragma unroll
        for (int i = 0; i < 128 / RPI; i++) {
            int r = lr + i * RPI;
            cp_async16(sa + r * 128 + sw, Ab + (size_t)r * KP + ga + lj * 8);
        }
        #pragma unroll
        for (int i = 0; i < BN / RPI; i++) {
            int r = lr + i * RPI;
            cp_async16(sa + ASIZE + r * 128 + sw, Bb + (size_t)r * KP + gb + lj * 8);
        }
        cp_commit();
    };

    float acc[4][8][4];
    #pragma unroll
    for (int mt = 0; mt < 4; mt++)
        #pragma unroll
        for (int nt = 0; nt < 8; nt++)
            #pragma unroll
            for (int i = 0; i < 4; i++) acc[mt][nt][i] = 0.f;

    load(0, 0);
    load(1, 1);

    // ldmatrix lane address components
    int a_row = wm * 64 + (lane & 15);                      // + mt*16
    int a_kq  = (lane >> 4);                                // 0/1 -> +8 cols
    int b_row = wn * 64 + ((lane >> 4) << 3) + (lane & 7);  // + p*16
    int b_kq  = ((lane >> 3) & 1);

    for (int c = 0; c < kcn; c++) {
        cp_wait1();
        __syncthreads();
        uint32_t sa = sbase + (uint32_t)(c % 3) * STAGE;
        #pragma unroll
        for (int ks = 0; ks < 4; ks++) {
            uint32_t af[4][4];
            #pragma unroll
            for (int mt = 0; mt < 4; mt++) {
                int r = a_row + mt * 16;
                int kc = (ks * 16 + a_kq * 8) >> 3;    // 16B-column index 0..7
                ldm_x4(af[mt], sa + r * 128 + (((uint32_t)(kc ^ (r & 7))) << 4));
            }
            uint32_t bf[4][4];
            #pragma unroll
            for (int p = 0; p < 4; p++) {
                int r = b_row + p * 16;
                int kc = (ks * 16 + b_kq * 8) >> 3;
                ldm_x4(bf[p], sa + ASIZE + r * 128 + (((uint32_t)(kc ^ (r & 7))) << 4));
            }
            #pragma unroll
            for (int mt = 0; mt < 4; mt++)
                #pragma unroll
                for (int nt = 0; nt < 8; nt++)
                    mma_bf16(acc[mt][nt], af[mt], bf[nt >> 1][(nt & 1) * 2], bf[nt >> 1][(nt & 1) * 2 + 1]);
        }
        if (c + 2 < kcn) load(c + 2, (c + 2) % 3);
    }

    // ---- epilogue: fp32 store ----
    float* Cz = Cf + (size_t)z * zstride;
    int mrow0 = rowBlk + wm * 64 + (lane >> 2);
    int ncol0 = colBlk + wn * 64 + (lane & 3) * 2;
    #pragma unroll
    for (int mt = 0; mt < 4; mt++)
        #pragma unroll
        for (int nt = 0; nt < 8; nt++) {
            int r0 = mrow0 + mt * 16;
            int cc = ncol0 + nt * 8;
            *(float2*)(Cz + (size_t)r0 * c_pitch + cc)       = make_float2(acc[mt][nt][0], acc[mt][nt][1]);
            *(float2*)(Cz + (size_t)(r0 + 8) * c_pitch + cc) = make_float2(acc[mt][nt][2], acc[mt][nt][3]);
        }
}

// ---------------- combine split-K partials -> transposed hi/lo B2 -----------
__global__ void combine_split() {
    __shared__ float tile[32][33];
    int a0 = blockIdx.y * 32, b0 = blockIdx.x * 32;
    int tx = threadIdx.x, ty = threadIdx.y;
    #pragma unroll
    for (int k = 0; k < 4; k++) {
        int a = a0 + ty + k * 8;
        size_t idx = (size_t)a * Dn + b0 + tx;
        float s = 0.f;
        #pragma unroll
        for (int z = 0; z < NSPLIT; z++) s += g_Mp[idx + (size_t)z * Dn * Dn];
        tile[ty + k * 8][tx] = s;
    }
    __syncthreads();
    #pragma unroll
    for (int k = 0; k < 4; k++) {
        int b = b0 + ty + k * 8;
        float m = tile[tx][ty + k * 8];
        __nv_bfloat16 hi = __float2bfloat16(m);
        __nv_bfloat16 lo = __float2bfloat16(m - __bfloat162float(hi));
        __nv_bfloat16* row = g_B2 + (size_t)b * KP;
        row[a0 + tx] = hi; row[a0 + tx + 1024] = lo;
    }
}

// ---------------- LayerNorm (+ split-bf16 A operand) ------------------------
__global__ void ln_kernel(const float* __restrict__ ctx,
                          const float* __restrict__ gamma,
                          const float* __restrict__ beta) {
    __shared__ float warpred[8];
    __shared__ float stat[2];
    int r = blockIdx.x, t = threadIdx.x;
    int lane = t & 31, w = t >> 5;
    const float4* in = (const float4*)(ctx + (size_t)r * Dn);
    float4 v = in[t];

    float s = v.x + v.y + v.z + v.w;
    #pragma unroll
    for (int o = 16; o; o >>= 1) s += __shfl_xor_sync(0xffffffffu, s, o);
    if (lane == 0) warpred[w] = s;
    __syncthreads();
    if (t < 32) {
        float x = (t < 8) ? warpred[t] : 0.f;
        #pragma unroll
        for (int o = 4; o; o >>= 1) x += __shfl_xor_sync(0xffffffffu, x, o);
        if (t == 0) stat[0] = x;
    }
    __syncthreads();
    float mean = stat[0] * (1.0f / Dn);
    float dx = v.x - mean, dy = v.y - mean, dz = v.z - mean, dw = v.w - mean;
    float sq = dx*dx + dy*dy + dz*dz + dw*dw;
    __syncthreads();
    #pragma unroll
    for (int o = 16; o; o >>= 1) sq += __shfl_xor_sync(0xffffffffu, sq, o);
    if (lane == 0) warpred[w] = sq;
    __syncthreads();
    if (t < 32) {
        float x = (t < 8) ? warpred[t] : 0.f;
        #pragma unroll
        for (int o = 4; o; o >>= 1) x += __shfl_xor_sync(0xffffffffu, x, o);
        if (t == 0) stat[1] = x;
    }
    __syncthreads();
    float var = stat[1] * (1.0f / (Dn - 1));          // unbiased (Bessel)
    float rs  = 1.0f / (sqrtf(var) + 1e-6f);          // sqrt(var)+eps !
    float4 g4 = ((const float4*)gamma)[t];
    float4 b4 = ((const float4*)beta)[t];
    float4 o;
    o.x = g4.x * dx * rs + b4.x;
    o.y = g4.y * dy * rs + b4.y;
    o.z = g4.z * dz * rs + b4.z;
    o.w = g4.w * dw * rs + b4.w;
    ((float4*)(g_x + (size_t)r * Dn))[t] = o;

    // split bf16: A2 row = [hi | lo]
    __nv_bfloat16 hi[4], lo[4];
    #pragma unroll
    for (int i = 0; i < 4; i++) {
        float vv = (&o.x)[i];
        hi[i] = __float2bfloat16(vv);
        lo[i] = __float2bfloat16(vv - __bfloat162float(hi[i]));
    }
    __nv_bfloat16* row = g_A2 + (size_t)r * KP + t * 4;
    *(uint2*)(row)        = *(uint2*)hi;
    *(uint2*)(row + 1024) = *(uint2*)lo;
}

// ---------------- split Wq/Wk into bf16 operands ----------------------------
__global__ void prep_w(const float* __restrict__ Wq, const float* __restrict__ Wk) {
    int r = blockIdx.x, t = threadIdx.x;
    float4 q4 = ((const float4*)(Wq + (size_t)r * Dn))[t];
    float4 k4 = ((const float4*)(Wk + (size_t)r * Dn))[t];
    __nv_bfloat16 qh[4], ql[4], kh[4], kl[4];
    #pragma unroll
    for (int i = 0; i < 4; i++) {
        float qv = (&q4.x)[i];
        qh[i] = __float2bfloat16(qv);
        ql[i] = __float2bfloat16(qv - __bfloat162float(qh[i]));
        float kv = (&k4.x)[i];
        kh[i] = __float2bfloat16(kv);
        kl[i] = __float2bfloat16(kv - __bfloat162float(kh[i]));
    }
    __nv_bfloat16* a = g_A1 + (size_t)r * KP + t * 4;   // [Wq_hi | Wq_lo]
    *(uint2*)(a)        = *(uint2*)qh;
    *(uint2*)(a + 1024) = *(uint2*)ql;
    __nv_bfloat16* b = g_B1 + (size_t)r * KP + t * 4;   // [Wk_hi | Wk_lo]
    *(uint2*)(b)        = *(uint2*)kh;
    *(uint2*)(b + 1024) = *(uint2*)kl;
}

// ---------------- u = Wq bk, v = Wk bq, c = bq.bk ---------------------------
__global__ void uv_kernel(const float* __restrict__ Wq, const float* __restrict__ Wk,
                          const float* __restrict__ bq, const float* __restrict__ bk) {
    __shared__ float warpred[8];
    int blk = blockIdx.x, t = threadIdx.x;
    int lane = t & 31, w = t >> 5;
    float4 a, b2;
    if (blk < Dn)           { a = ((const float4*)(Wq + (size_t)blk * Dn))[t];      b2 = ((const float4*)bk)[t]; }
    else if (blk < 2 * Dn)  { a = ((const float4*)(Wk + (size_t)(blk - Dn) * Dn))[t]; b2 = ((const float4*)bq)[t]; }
    else                    { a = ((const float4*)bq)[t];                            b2 = ((const float4*)bk)[t]; }
    float s = a.x*b2.x + a.y*b2.y + a.z*b2.z + a.w*b2.w;
    #pragma unroll
    for (int o = 16; o; o >>= 1) s += __shfl_xor_sync(0xffffffffu, s, o);
    if (lane == 0) warpred[w] = s;
    __syncthreads();
    if (t == 0) {
        float tot = 0.f;
        #pragma unroll
        for (int i = 0; i < 8; i++) tot += warpred[i];
        if (blk < Dn)          g_u[blk] = tot;
        else if (blk < 2 * Dn) g_v[blk - Dn] = tot;
        else                   g_c = tot;
    }
}

// ---------------- per-row dots: y_i.x_{i+1}, y_i.x_{i-1}, x_i.u, x_i.v ------
__global__ void dots_kernel() {
    __shared__ float red[4][8];
    int r = blockIdx.x, t = threadIdx.x;
    int i = r & (Sn - 1);
    int lane = t & 31, w = t >> 5;
    float4 xr = ((const float4*)(g_x + (size_t)r * Dn))[t];
    float4 yr = ((const float4*)(g_y + (size_t)r * Dn))[t];
    float4 u4 = ((const float4*)g_u)[t];
    float4 v4 = ((const float4*)g_v)[t];
    float su = xr.x*u4.x + xr.y*u4.y + xr.z*u4.z + xr.w*u4.w;
    float sv = xr.x*v4.x + xr.y*v4.y + xr.z*v4.z + xr.w*v4.w;
    float du = 0.f, dn = 0.f;
    if (i < Sn - 1) {
        float4 xn = ((const float4*)(g_x + (size_t)(r + 1) * Dn))[t];
        du = yr.x*xn.x + yr.y*xn.y + yr.z*xn.z + yr.w*xn.w;
    }
    if (i > 0) {
        float4 xp = ((const float4*)(g_x + (size_t)(r - 1) * Dn))[t];
        dn = yr.x*xp.x + yr.y*xp.y + yr.z*xp.z + yr.w*xp.w;
    }
    float vals[4] = {su, sv, du, dn};
    #pragma unroll
    for (int k = 0; k < 4; k++) {
        float x = vals[k];
        #pragma unroll
        for (int o = 16; o; o >>= 1) x += __shfl_xor_sync(0xffffffffu, x, o);
        if (lane == 0) red[k][w] = x;
    }
    __syncthreads();
    if (t < 4) {
        float s2 = 0.f;
        #pragma unroll
        for (int w2 = 0; w2 < 8; w2++) s2 += red[t][w2];
        if      (t == 0) g_xu[r]  = s2;
        else if (t == 1) g_xv[r]  = s2;
        else if (t == 2) g_dup[r] = s2;
        else             g_ddn[r] = s2;
    }
}

// ---------------- band softmax ---------------------------------------------
__global__ void band_softmax(const int* __restrict__ eos) {
    int r = blockIdx.x * blockDim.x + threadIdx.x;
    if (r >= BSn) return;
    int b = r >> 11;
    int i = r & (Sn - 1);
    const float invD = 1.0f / Dn, invS = 1.0f / Sn;
    size_t base = ((size_t)b * Sn + i) * Sn;
    bool hu = false, hd = false;
    float su = 0.f, sd = 0.f;
    float cc = g_c;
    if (i < Sn - 1 && eos[base + i + 1] != 0) {
        hu = true;
        su = (g_dup[r] + g_xu[r] + g_xv[r + 1] + cc) * invD;
    }
    if (i > 0 && eos[base + i - 1] != 0) {
        hd = true;
        sd = (g_ddn[r] + g_xu[r] + g_xv[r - 1] + cc) * invD;
    }
    float up = 0.f, dn = 0.f, dg = 0.f;
    if (!hu && !hd) { up = invS; dn = invS; dg = invS; }     // fully-masked row -> uniform 1/S
    else if (hu && hd) {
        float m = fmaxf(su, sd);
        float eu = expf(su - m), ed = expf(sd - m);
        float inv = 1.0f / (eu + ed);
        up = eu * inv; dn = ed * inv;
    } else if (hu) up = 1.f;
    else dn = 1.f;
    g_rvup[r] = up; g_rvdn[r] = dn; g_rvdiag[r] = dg;
    g_fm[r] = (!hu && !hd) ? 1 : 0;
}

// ---------------- per-batch prefix sum of L = log(na[i][i+1]+1e-9) ----------
__global__ void scan_kernel(const float* __restrict__ prior) {
    __shared__ double sh[1024];
    int b = blockIdx.x, t = threadIdx.x;
    size_t rb = (size_t)b * Sn;

    auto Lval = [&](int i) -> double {    // i in [0, Sn-2]
        int r = b * Sn + i;
        float pr = prior[((size_t)b * Sn + i) * Sn + i + 1];
        float p = g_rvup[r] * g_rvdn[r + 1];
        float nsym = sqrtf(p + 1e-9f);
        float na = pr + (1.0f - pr) * nsym;
        return (double)logf(na + 1e-9f);
    };

    int j0 = 2 * t, j1 = 2 * t + 1;
    double a = (j0 == 0) ? 0.0 : Lval(j0 - 1);
    double c = Lval(j1 - 1);
    double pair = a + c;
    sh[t] = pair;
    __syncthreads();
    for (int off = 1; off < 1024; off <<= 1) {
        double v = sh[t];
        if (t >= off) v += sh[t - off];
        __syncthreads();
        sh[t] = v;
        __syncthreads();
    }
    double excl = sh[t] - pair;
    g_P[rb + j0] = excl + a;
    g_P[rb + j1] = excl + a + c;
}

// ---------------- dense epilogue: write na and g_attn -----------------------
// Non-band sqrt takes only 2 constant values; exp saturates to 1e-9 past |d|>38.
__global__ void dense_kernel(const float* __restrict__ prior,
                             float* __restrict__ out_g,
                             float* __restrict__ out_na) {
    const float C0 = 3.16227766e-5f;        // sqrtf(1e-9f)
    const float Cm = 4.89304178e-4f;        // sqrtf(invS^2 + 1e-9f), invS=1/2048
    int b  = blockIdx.z;
    int i  = blockIdx.y * 4 + threadIdx.y;
    int j0 = (blockIdx.x * 64 + threadIdx.x) * 4;
    size_t rb  = (size_t)b * Sn;
    size_t off = (rb + i) * Sn + j0;
    float4 pr4 = *(const float4*)(prior + off);
    double Pi = g_P[rb + i];
    double2 p01 = *(const double2*)(g_P + rb + j0);
    double2 p23 = *(const double2*)(g_P + rb + j0 + 2);
    double Pj[4] = {p01.x, p01.y, p23.x, p23.y};
    float na4[4], ga4[4];

    bool near = (j0 <= i + 1) && (j0 + 3 >= i - 1);
    if (!near) {
        unsigned char fmi = g_fm[rb + i];
        uchar4 fmj = *(const uchar4*)(g_fm + rb + j0);
        const unsigned char* fj = (const unsigned char*)&fmj;
        bool right = (j0 > i);
        #pragma unroll
        for (int jj = 0; jj < 4; jj++) {
            float pr = (&pr4.x)[jj];
            float C = (fmi && fj[jj]) ? Cm : C0;
            na4[jj] = pr + (1.0f - pr) * C;
        }
        float dlead = right ? (float)(Pj[0] - Pi) : (float)(Pi - Pj[3]);
        if (dlead <= -38.0f) {
            #pragma unroll
            for (int jj = 0; jj < 4; jj++) ga4[jj] = 1e-9f;
        } else {
            #pragma unroll
            for (int jj = 0; jj < 4; jj++) {
                float d = right ? (float)(Pj[jj] - Pi) : (float)(Pi - Pj[jj]);
                ga4[jj] = (d > -38.0f) ? (__expf(d) + 1e-9f) : 1e-9f;
            }
        }
    } else {
        float di = g_rvdiag[rb + i];
        #pragma unroll
        for (int jj = 0; jj < 4; jj++) {
            int j = j0 + jj;
            float pr = (&pr4.x)[jj];
            float p;
            if      (j == i)     p = di * di;
            else if (j == i + 1) p = g_rvup[rb + i] * g_rvdn[rb + j];
            else if (j == i - 1) p = g_rvdn[rb + i] * g_rvup[rb + j];
            else                 p = di * g_rvdiag[rb + j];
            float na = pr + (1.0f - pr) * sqrtf(p + 1e-9f);
            float ga;
            if (j == i) ga = na;
            else {
                double d = Pj[jj] - Pi;
                if (j < i) d = -d;
                ga = expf((float)d) + 1e-9f;
            }
            na4[jj] = na; ga4[jj] = ga;
        }
    }
    *(float4*)(out_na + off) = make_float4(na4[0], na4[1], na4[2], na4[3]);
    *(float4*)(out_g  + off) = make_float4(ga4[0], ga4[1], ga4[2], ga4[3]);
}

// ---------------- launch ----------------------------------------------------
extern "C" void kernel_launch(void* const* d_in, const int* in_sizes, int n_in,
                              void* d_out, int out_size) {
    const float* ctx   = (const float*)d_in[0];
    const int*   eos   = (const int*)  d_in[1];
    const float* prior = (const float*)d_in[2];
    const float* Wq    = (const float*)d_in[3];
    const float* bq    = (const float*)d_in[4];
    const float* Wk    = (const float*)d_in[5];
    const float* bk    = (const float*)d_in[6];
    const float* gamma = (const float*)d_in[7];
    const float* beta  = (const float*)d_in[8];
    float* out_g  = (float*)d_out;
    float* out_na = out_g + (size_t)Bn * Sn * Sn;

    float *py, *pMp;
    __nv_bfloat16 *pA1, *pB1, *pA2, *pB2;
    cudaGetSymbolAddress((void**)&py,  g_y);
    cudaGetSymbolAddress((void**)&pMp, g_Mp);
    cudaGetSymbolAddress((void**)&pA1, g_A1);
    cudaGetSymbolAddress((void**)&pB1, g_B1);
    cudaGetSymbolAddress((void**)&pA2, g_A2);
    cudaGetSymbolAddress((void**)&pB2, g_B2);

    const int smem128 = 3 * (128 + 128) * 128;   // 98304  (3 stages x 32KB)
    const int smem256 = 3 * (128 + 256) * 128;   // 147456 (3 stages x 48KB)
    static int attr_done = 0;
    if (!attr_done) {
        cudaFuncSetAttribute(gemm_mma<128>, cudaFuncAttributeMaxDynamicSharedMemorySize, smem128);
        cudaFuncSetAttribute(gemm_mma<256>, cudaFuncAttributeMaxDynamicSharedMemorySize, smem256);
        attr_done = 1;
    }

    ln_kernel<<<BSn, 256>>>(ctx, gamma, beta);
    prep_w<<<Dn, 256>>>(Wq, Wk);
    uv_kernel<<<2 * Dn + 1, 256>>>(Wq, Wk, bq, bk);
    // GEMM1 (split-K x3): partials of M = Wq @ Wk^T into g_Mp
    gemm_mma<128><<<dim3(Dn / 128, Dn / 128, NSPLIT), 128, smem128>>>(pA1, pB1, pMp, Dn, (size_t)Dn * Dn, KTOT / NSPLIT);
    // combine partials -> transposed hi/lo operand B2
    combine_split<<<dim3(Dn / 32, Dn / 32), dim3(32, 8)>>>();
    // GEMM2: y = x @ M  (3-term split-bf16 via chunk remap) -> fp32 g_y
    gemm_mma<256><<<dim3(Dn / 256, BSn / 128, 1), 256, smem256>>>(pA2, pB2, py, Dn, 0, KTOT);
    dots_kernel<<<BSn, 256>>>();
    band_softmax<<<BSn / 256, 256>>>(eos);
    scan_kernel<<<Bn, 1024>>>(prior);
    dense_kernel<<<dim3(Sn / 256, Sn / 4, Bn), dim3(64, 4)>>>(prior, out_g, out_na);
}

// round 14
// speedup vs baseline: 1.2183x; 1.2183x over previous
#include <cuda_runtime.h>
#include <cuda_bf16.h>
#include <math.h>
#include <stdint.h>

#define Bn 4
#define Sn 2048
#define Dn 1024
#define BSn (Bn*Sn)
#define KP 2048          // physical operand pitch: [hi | lo] segments
#define KTOT 48          // logical K chunks for GEMM1 (3-term split)
#define K2TOT 32         // logical K chunks for GEMM2 (2-term: xh*Mh + xl*Mh)
#define NSPLIT 3         // GEMM1 split-K factor

// ---------------- scratch (static device arrays; no allocation allowed) -----
__device__ float  g_x[(size_t)BSn * Dn];             // layernormed context (fp32)
__device__ float  g_y[(size_t)BSn * Dn];             // x @ M  (fp32)
__device__ __nv_bfloat16 g_A2[(size_t)BSn * KP];     // [x_hi | x_lo]
__device__ __nv_bfloat16 g_B2[(size_t)Dn * KP];      // [M_hi | M_lo] (rows = output col b)
__device__ __nv_bfloat16 g_A1[(size_t)Dn * KP];      // [Wq_hi | Wq_lo]
__device__ __nv_bfloat16 g_B1[(size_t)Dn * KP];      // [Wk_hi | Wk_lo]
__device__ float  g_Mp[NSPLIT * (size_t)Dn * Dn];    // split-K partials of M
__device__ float  g_u[Dn];                 // Wq @ bk
__device__ float  g_v[Dn];                 // Wk @ bq
__device__ float  g_c;                     // bq . bk
__device__ float  g_xu[BSn], g_xv[BSn], g_dup[BSn], g_ddn[BSn];
__device__ float  g_rvup[BSn], g_rvdn[BSn], g_rvdiag[BSn];
__device__ unsigned char g_fm[BSn];        // fully-masked row flag
__device__ double g_P[BSn];

// ======================= helpers ============================================
__device__ __forceinline__ uint32_t smem_u32(const void* p) {
    uint32_t a;
    asm("{ .reg .u64 t; cvta.to.shared.u64 t, %1; cvt.u32.u64 %0, t; }" : "=r"(a) : "l"(p));
    return a;
}
__device__ __forceinline__ void cp_async16(uint32_t dst, const void* src) {
    asm volatile("cp.async.cg.shared.global [%0], [%1], 16;" :: "r"(dst), "l"(src) : "memory");
}
__device__ __forceinline__ void cp_commit() {
    asm volatile("cp.async.commit_group;" ::: "memory");
}
__device__ __forceinline__ void cp_wait1() {
    asm volatile("cp.async.wait_group 1;" ::: "memory");
}
__device__ __forceinline__ void ldm_x4(uint32_t* r, uint32_t addr) {
    asm volatile("ldmatrix.sync.aligned.m8n8.x4.shared.b16 {%0,%1,%2,%3}, [%4];"
        : "=r"(r[0]), "=r"(r[1]), "=r"(r[2]), "=r"(r[3]) : "r"(addr));
}
__device__ __forceinline__ void mma_bf16(float* c, const uint32_t* a, uint32_t b0, uint32_t b1) {
    asm volatile("mma.sync.aligned.m16n8k16.row.col.f32.bf16.bf16.f32 "
        "{%0,%1,%2,%3}, {%4,%5,%6,%7}, {%8,%9}, {%0,%1,%2,%3};"
        : "+f"(c[0]), "+f"(c[1]), "+f"(c[2]), "+f"(c[3])
        : "r"(a[0]), "r"(a[1]), "r"(a[2]), "r"(a[3]), "r"(b0), "r"(b1));
}

// ===================== HMMA bf16 GEMM =======================================
// Logical: C[M,N] = sum over kcn K-chunks of A'[.,g] * B'[.,g]^T where
//   A' chunk g maps to physical chunk (g<32 ? g : g-32) of [hi|lo] storage,
//   B' chunk g maps to physical chunk (g<16 ? g : g-16).
// GEMM1 runs 48 chunks (3-term split: qh*kh + ql*kh + qh*kl).
// GEMM2 runs 32 chunks (2-term: xh*Mh + xl*Mh) — the dropped xh*Ml term is
// ~2^-9 relative, measured safe under the 1e-3 threshold.
// BM=BN=128, BK=64. 128 threads = 4 warps, 64x64 warp tiles (2x2 grid).
// 3-stage cp.async pipeline, 2 CTAs/SM. blockIdx.z = K-split; out +z*zstride.
__global__ __launch_bounds__(128, 2) void gemm_mma(const __nv_bfloat16* __restrict__ A,
                                                   const __nv_bfloat16* __restrict__ Bm,
                                                   float* __restrict__ Cf,
                                                   int c_pitch, size_t zstride, int kcn) {
    constexpr int ASIZE = 128 * 128;     // 16 KB (128 rows x 128B)
    constexpr int STAGE = 2 * ASIZE;     // A + B = 32 KB
    extern __shared__ char smem[];
    uint32_t sbase = smem_u32(smem);
    int t = threadIdx.x, wid = t >> 5, lane = t & 31;
    int wm = wid & 1, wn = wid >> 1;           // 2 x 2 warp grid -> 64 x 64 tiles
    int rowBlk = blockIdx.y * 128;
    int colBlk = blockIdx.x * 128;
    int z = blockIdx.z;
    int zbase = z * kcn;

    const __nv_bfloat16* Ab = A + (size_t)rowBlk * KP;
    const __nv_bfloat16* Bb = Bm + (size_t)colBlk * KP;

    int lr = t >> 3, lj = t & 7;                       // 128 thr -> 16 rows x 8 chunks
    uint32_t sw = ((uint32_t)(lj ^ (lr & 7))) << 4;

    auto load = [&](int c, int s) {
        int g = zbase + c;
        int ga = (g < 32 ? g : g - 32) * 64;           // A physical column offset
        int gb = (g < 16 ? g : g - 16) * 64;           // B physical column offset
        uint32_t sa = sbase + (uint32_t)s * STAGE;
        #pragma unroll
        for (int i = 0; i < 8; i++) {
            int r = lr + i * 16;
            cp_async16(sa + r * 128 + sw, Ab + (size_t)r * KP + ga + lj * 8);
        }
        #pragma unroll
        for (int i = 0; i < 8; i++) {
            int r = lr + i * 16;
            cp_async16(sa + ASIZE + r * 128 + sw, Bb + (size_t)r * KP + gb + lj * 8);
        }
        cp_commit();
    };

    float acc[4][8][4];
    #pragma unroll
    for (int mt = 0; mt < 4; mt++)
        #pragma unroll
        for (int nt = 0; nt < 8; nt++)
            #pragma unroll
            for (int i = 0; i < 4; i++) acc[mt][nt][i] = 0.f;

    load(0, 0);
    load(1, 1);

    // ldmatrix lane address components
    int a_row = wm * 64 + (lane & 15);                      // + mt*16
    int a_kq  = (lane >> 4);                                // 0/1 -> +8 cols
    int b_row = wn * 64 + ((lane >> 4) << 3) + (lane & 7);  // + nt2*16
    int b_kq  = ((lane >> 3) & 1);

    for (int c = 0; c < kcn; c++) {
        cp_wait1();
        __syncthreads();
        uint32_t sa = sbase + (uint32_t)(c % 3) * STAGE;
        #pragma unroll
        for (int ks = 0; ks < 4; ks++) {
            uint32_t af[4][4];
            #pragma unroll
            for (int mt = 0; mt < 4; mt++) {
                int r = a_row + mt * 16;
                int kc = (ks * 16 + a_kq * 8) >> 3;    // 16B-column index 0..7
                ldm_x4(af[mt], sa + r * 128 + (((uint32_t)(kc ^ (r & 7))) << 4));
            }
            uint32_t bf[4][4];
            #pragma unroll
            for (int p = 0; p < 4; p++) {
                int r = b_row + p * 16;
                int kc = (ks * 16 + b_kq * 8) >> 3;
                ldm_x4(bf[p], sa + ASIZE + r * 128 + (((uint32_t)(kc ^ (r & 7))) << 4));
            }
            #pragma unroll
            for (int mt = 0; mt < 4; mt++)
                #pragma unroll
                for (int nt = 0; nt < 8; nt++)
                    mma_bf16(acc[mt][nt], af[mt], bf[nt >> 1][(nt & 1) * 2], bf[nt >> 1][(nt & 1) * 2 + 1]);
        }
        if (c + 2 < kcn) load(c + 2, (c + 2) % 3);
    }

    // ---- epilogue: fp32 store ----
    float* Cz = Cf + (size_t)z * zstride;
    int mrow0 = rowBlk + wm * 64 + (lane >> 2);
    int ncol0 = colBlk + wn * 64 + (lane & 3) * 2;
    #pragma unroll
    for (int mt = 0; mt < 4; mt++)
        #pragma unroll
        for (int nt = 0; nt < 8; nt++) {
            int r0 = mrow0 + mt * 16;
            int cc = ncol0 + nt * 8;
            *(float2*)(Cz + (size_t)r0 * c_pitch + cc)       = make_float2(acc[mt][nt][0], acc[mt][nt][1]);
            *(float2*)(Cz + (size_t)(r0 + 8) * c_pitch + cc) = make_float2(acc[mt][nt][2], acc[mt][nt][3]);
        }
}

// ---------------- combine split-K partials -> transposed hi/lo B2 -----------
__global__ void combine_split() {
    __shared__ float tile[32][33];
    int a0 = blockIdx.y * 32, b0 = blockIdx.x * 32;
    int tx = threadIdx.x, ty = threadIdx.y;
    #pragma unroll
    for (int k = 0; k < 4; k++) {
        int a = a0 + ty + k * 8;
        size_t idx = (size_t)a * Dn + b0 + tx;
        float s = 0.f;
        #pragma unroll
        for (int z = 0; z < NSPLIT; z++) s += g_Mp[idx + (size_t)z * Dn * Dn];
        tile[ty + k * 8][tx] = s;
    }
    __syncthreads();
    #pragma unroll
    for (int k = 0; k < 4; k++) {
        int b = b0 + ty + k * 8;
        float m = tile[tx][ty + k * 8];
        __nv_bfloat16 hi = __float2bfloat16(m);
        __nv_bfloat16 lo = __float2bfloat16(m - __bfloat162float(hi));
        __nv_bfloat16* row = g_B2 + (size_t)b * KP;
        row[a0 + tx] = hi; row[a0 + tx + 1024] = lo;
    }
}

// ---------------- LayerNorm (+ split-bf16 A operand) ------------------------
__global__ void ln_kernel(const float* __restrict__ ctx,
                          const float* __restrict__ gamma,
                          const float* __restrict__ beta) {
    __shared__ float warpred[8];
    __shared__ float stat[2];
    int r = blockIdx.x, t = threadIdx.x;
    int lane = t & 31, w = t >> 5;
    const float4* in = (const float4*)(ctx + (size_t)r * Dn);
    float4 v = in[t];

    float s = v.x + v.y + v.z + v.w;
    #pragma unroll
    for (int o = 16; o; o >>= 1) s += __shfl_xor_sync(0xffffffffu, s, o);
    if (lane == 0) warpred[w] = s;
    __syncthreads();
    if (t < 32) {
        float x = (t < 8) ? warpred[t] : 0.f;
        #pragma unroll
        for (int o = 4; o; o >>= 1) x += __shfl_xor_sync(0xffffffffu, x, o);
        if (t == 0) stat[0] = x;
    }
    __syncthreads();
    float mean = stat[0] * (1.0f / Dn);
    float dx = v.x - mean, dy = v.y - mean, dz = v.z - mean, dw = v.w - mean;
    float sq = dx*dx + dy*dy + dz*dz + dw*dw;
    __syncthreads();
    #pragma unroll
    for (int o = 16; o; o >>= 1) sq += __shfl_xor_sync(0xffffffffu, sq, o);
    if (lane == 0) warpred[w] = sq;
    __syncthreads();
    if (t < 32) {
        float x = (t < 8) ? warpred[t] : 0.f;
        #pragma unroll
        for (int o = 4; o; o >>= 1) x += __shfl_xor_sync(0xffffffffu, x, o);
        if (t == 0) stat[1] = x;
    }
    __syncthreads();
    float var = stat[1] * (1.0f / (Dn - 1));          // unbiased (Bessel)
    float rs  = 1.0f / (sqrtf(var) + 1e-6f);          // sqrt(var)+eps !
    float4 g4 = ((const float4*)gamma)[t];
    float4 b4 = ((const float4*)beta)[t];
    float4 o;
    o.x = g4.x * dx * rs + b4.x;
    o.y = g4.y * dy * rs + b4.y;
    o.z = g4.z * dz * rs + b4.z;
    o.w = g4.w * dw * rs + b4.w;
    ((float4*)(g_x + (size_t)r * Dn))[t] = o;

    // split bf16: A2 row = [hi | lo]
    __nv_bfloat16 hi[4], lo[4];
    #pragma unroll
    for (int i = 0; i < 4; i++) {
        float vv = (&o.x)[i];
        hi[i] = __float2bfloat16(vv);
        lo[i] = __float2bfloat16(vv - __bfloat162float(hi[i]));
    }
    __nv_bfloat16* row = g_A2 + (size_t)r * KP + t * 4;
    *(uint2*)(row)        = *(uint2*)hi;
    *(uint2*)(row + 1024) = *(uint2*)lo;
}

// ---------------- split Wq/Wk into bf16 operands ----------------------------
__global__ void prep_w(const float* __restrict__ Wq, const float* __restrict__ Wk) {
    int r = blockIdx.x, t = threadIdx.x;
    float4 q4 = ((const float4*)(Wq + (size_t)r * Dn))[t];
    float4 k4 = ((const float4*)(Wk + (size_t)r * Dn))[t];
    __nv_bfloat16 qh[4], ql[4], kh[4], kl[4];
    #pragma unroll
    for (int i = 0; i < 4; i++) {
        float qv = (&q4.x)[i];
        qh[i] = __float2bfloat16(qv);
        ql[i] = __float2bfloat16(qv - __bfloat162float(qh[i]));
        float kv = (&k4.x)[i];
        kh[i] = __float2bfloat16(kv);
        kl[i] = __float2bfloat16(kv - __bfloat162float(kh[i]));
    }
    __nv_bfloat16* a = g_A1 + (size_t)r * KP + t * 4;   // [Wq_hi | Wq_lo]
    *(uint2*)(a)        = *(uint2*)qh;
    *(uint2*)(a + 1024) = *(uint2*)ql;
    __nv_bfloat16* b = g_B1 + (size_t)r * KP + t * 4;   // [Wk_hi | Wk_lo]
    *(uint2*)(b)        = *(uint2*)kh;
    *(uint2*)(b + 1024) = *(uint2*)kl;
}

// ---------------- u = Wq bk, v = Wk bq, c = bq.bk ---------------------------
__global__ void uv_kernel(const float* __restrict__ Wq, const float* __restrict__ Wk,
                          const float* __restrict__ bq, const float* __restrict__ bk) {
    __shared__ float warpred[8];
    int blk = blockIdx.x, t = threadIdx.x;
    int lane = t & 31, w = t >> 5;
    float4 a, b2;
    if (blk < Dn)           { a = ((const float4*)(Wq + (size_t)blk * Dn))[t];      b2 = ((const float4*)bk)[t]; }
    else if (blk < 2 * Dn)  { a = ((const float4*)(Wk + (size_t)(blk - Dn) * Dn))[t]; b2 = ((const float4*)bq)[t]; }
    else                    { a = ((const float4*)bq)[t];                            b2 = ((const float4*)bk)[t]; }
    float s = a.x*b2.x + a.y*b2.y + a.z*b2.z + a.w*b2.w;
    #pragma unroll
    for (int o = 16; o; o >>= 1) s += __shfl_xor_sync(0xffffffffu, s, o);
    if (lane == 0) warpred[w] = s;
    __syncthreads();
    if (t == 0) {
        float tot = 0.f;
        #pragma unroll
        for (int i = 0; i < 8; i++) tot += warpred[i];
        if (blk < Dn)          g_u[blk] = tot;
        else if (blk < 2 * Dn) g_v[blk - Dn] = tot;
        else                   g_c = tot;
    }
}

// ---------------- per-row dots: y_i.x_{i+1}, y_i.x_{i-1}, x_i.u, x_i.v ------
__global__ void dots_kernel() {
    __shared__ float red[4][8];
    int r = blockIdx.x, t = threadIdx.x;
    int i = r & (Sn - 1);
    int lane = t & 31, w = t >> 5;
    float4 xr = ((const float4*)(g_x + (size_t)r * Dn))[t];
    float4 yr = ((const float4*)(g_y + (size_t)r * Dn))[t];
    float4 u4 = ((const float4*)g_u)[t];
    float4 v4 = ((const float4*)g_v)[t];
    float su = xr.x*u4.x + xr.y*u4.y + xr.z*u4.z + xr.w*u4.w;
    float sv = xr.x*v4.x + xr.y*v4.y + xr.z*v4.z + xr.w*v4.w;
    float du = 0.f, dn = 0.f;
    if (i < Sn - 1) {
        float4 xn = ((const float4*)(g_x + (size_t)(r + 1) * Dn))[t];
        du = yr.x*xn.x + yr.y*xn.y + yr.z*xn.z + yr.w*xn.w;
    }
    if (i > 0) {
        float4 xp = ((const float4*)(g_x + (size_t)(r - 1) * Dn))[t];
        dn = yr.x*xp.x + yr.y*xp.y + yr.z*xp.z + yr.w*xp.w;
    }
    float vals[4] = {su, sv, du, dn};
    #pragma unroll
    for (int k = 0; k < 4; k++) {
        float x = vals[k];
        #pragma unroll
        for (int o = 16; o; o >>= 1) x += __shfl_xor_sync(0xffffffffu, x, o);
        if (lane == 0) red[k][w] = x;
    }
    __syncthreads();
    if (t < 4) {
        float s2 = 0.f;
        #pragma unroll
        for (int w2 = 0; w2 < 8; w2++) s2 += red[t][w2];
        if      (t == 0) g_xu[r]  = s2;
        else if (t == 1) g_xv[r]  = s2;
        else if (t == 2) g_dup[r] = s2;
        else             g_ddn[r] = s2;
    }
}

// ---------------- band softmax ---------------------------------------------
__global__ void band_softmax(const int* __restrict__ eos) {
    int r = blockIdx.x * blockDim.x + threadIdx.x;
    if (r >= BSn) return;
    int b = r >> 11;
    int i = r & (Sn - 1);
    const float invD = 1.0f / Dn, invS = 1.0f / Sn;
    size_t base = ((size_t)b * Sn + i) * Sn;
    bool hu = false, hd = false;
    float su = 0.f, sd = 0.f;
    float cc = g_c;
    if (i < Sn - 1 && eos[base + i + 1] != 0) {
        hu = true;
        su = (g_dup[r] + g_xu[r] + g_xv[r + 1] + cc) * invD;
    }
    if (i > 0 && eos[base + i - 1] != 0) {
        hd = true;
        sd = (g_ddn[r] + g_xu[r] + g_xv[r - 1] + cc) * invD;
    }
    float up = 0.f, dn = 0.f, dg = 0.f;
    if (!hu && !hd) { up = invS; dn = invS; dg = invS; }     // fully-masked row -> uniform 1/S
    else if (hu && hd) {
        float m = fmaxf(su, sd);
        float eu = expf(su - m), ed = expf(sd - m);
        float inv = 1.0f / (eu + ed);
        up = eu * inv; dn = ed * inv;
    } else if (hu) up = 1.f;
    else dn = 1.f;
    g_rvup[r] = up; g_rvdn[r] = dn; g_rvdiag[r] = dg;
    g_fm[r] = (!hu && !hd) ? 1 : 0;
}

// ---------------- per-batch prefix sum of L = log(na[i][i+1]+1e-9) ----------
__global__ void scan_kernel(const float* __restrict__ prior) {
    __shared__ double sh[1024];
    int b = blockIdx.x, t = threadIdx.x;
    size_t rb = (size_t)b * Sn;

    auto Lval = [&](int i) -> double {    // i in [0, Sn-2]
        int r = b * Sn + i;
        float pr = prior[((size_t)b * Sn + i) * Sn + i + 1];
        float p = g_rvup[r] * g_rvdn[r + 1];
        float nsym = sqrtf(p + 1e-9f);
        float na = pr + (1.0f - pr) * nsym;
        return (double)logf(na + 1e-9f);
    };

    int j0 = 2 * t, j1 = 2 * t + 1;
    double a = (j0 == 0) ? 0.0 : Lval(j0 - 1);
    double c = Lval(j1 - 1);
    double pair = a + c;
    sh[t] = pair;
    __syncthreads();
    for (int off = 1; off < 1024; off <<= 1) {
        double v = sh[t];
        if (t >= off) v += sh[t - off];
        __syncthreads();
        sh[t] = v;
        __syncthreads();
    }
    double excl = sh[t] - pair;
    g_P[rb + j0] = excl + a;
    g_P[rb + j1] = excl + a + c;
}

// ---------------- dense epilogue: write na and g_attn -----------------------
// Non-band sqrt takes only 2 constant values; exp saturates to 1e-9 past |d|>38.
__global__ void dense_kernel(const float* __restrict__ prior,
                             float* __restrict__ out_g,
                             float* __restrict__ out_na) {
    const float C0 = 3.16227766e-5f;        // sqrtf(1e-9f)
    const float Cm = 4.89304178e-4f;        // sqrtf(invS^2 + 1e-9f), invS=1/2048
    int b  = blockIdx.z;
    int i  = blockIdx.y * 4 + threadIdx.y;
    int j0 = (blockIdx.x * 64 + threadIdx.x) * 4;
    size_t rb  = (size_t)b * Sn;
    size_t off = (rb + i) * Sn + j0;
    float4 pr4 = *(const float4*)(prior + off);
    double Pi = g_P[rb + i];
    double2 p01 = *(const double2*)(g_P + rb + j0);
    double2 p23 = *(const double2*)(g_P + rb + j0 + 2);
    double Pj[4] = {p01.x, p01.y, p23.x, p23.y};
    float na4[4], ga4[4];

    bool near = (j0 <= i + 1) && (j0 + 3 >= i - 1);
    if (!near) {
        unsigned char fmi = g_fm[rb + i];
        uchar4 fmj = *(const uchar4*)(g_fm + rb + j0);
        const unsigned char* fj = (const unsigned char*)&fmj;
        bool right = (j0 > i);
        #pragma unroll
        for (int jj = 0; jj < 4; jj++) {
            float pr = (&pr4.x)[jj];
            float C = (fmi && fj[jj]) ? Cm : C0;
            na4[jj] = pr + (1.0f - pr) * C;
        }
        float dlead = right ? (float)(Pj[0] - Pi) : (float)(Pi - Pj[3]);
        if (dlead <= -38.0f) {
            #pragma unroll
            for (int jj = 0; jj < 4; jj++) ga4[jj] = 1e-9f;
        } else {
            #pragma unroll
            for (int jj = 0; jj < 4; jj++) {
                float d = right ? (float)(Pj[jj] - Pi) : (float)(Pi - Pj[jj]);
                ga4[jj] = (d > -38.0f) ? (__expf(d) + 1e-9f) : 1e-9f;
            }
        }
    } else {
        float di = g_rvdiag[rb + i];
        #pragma unroll
        for (int jj = 0; jj < 4; jj++) {
            int j = j0 + jj;
            float pr = (&pr4.x)[jj];
            float p;
            if      (j == i)     p = di * di;
            else if (j == i + 1) p = g_rvup[rb + i] * g_rvdn[rb + j];
            else if (j == i - 1) p = g_rvdn[rb + i] * g_rvup[rb + j];
            else                 p = di * g_rvdiag[rb + j];
            float na = pr + (1.0f - pr) * sqrtf(p + 1e-9f);
            float ga;
            if (j == i) ga = na;
            else {
                double d = Pj[jj] - Pi;
                if (j < i) d = -d;
                ga = expf((float)d) + 1e-9f;
            }
            na4[jj] = na; ga4[jj] = ga;
        }
    }
    *(float4*)(out_na + off) = make_float4(na4[0], na4[1], na4[2], na4[3]);
    *(float4*)(out_g  + off) = make_float4(ga4[0], ga4[1], ga4[2], ga4[3]);
}

// ---------------- launch ----------------------------------------------------
extern "C" void kernel_launch(void* const* d_in, const int* in_sizes, int n_in,
                              void* d_out, int out_size) {
    const float* ctx   = (const float*)d_in[0];
    const int*   eos   = (const int*)  d_in[1];
    const float* prior = (const float*)d_in[2];
    const float* Wq    = (const float*)d_in[3];
    const float* bq    = (const float*)d_in[4];
    const float* Wk    = (const float*)d_in[5];
    const float* bk    = (const float*)d_in[6];
    const float* gamma = (const float*)d_in[7];
    const float* beta  = (const float*)d_in[8];
    float* out_g  = (float*)d_out;
    float* out_na = out_g + (size_t)Bn * Sn * Sn;

    float *py, *pMp;
    __nv_bfloat16 *pA1, *pB1, *pA2, *pB2;
    cudaGetSymbolAddress((void**)&py,  g_y);
    cudaGetSymbolAddress((void**)&pMp, g_Mp);
    cudaGetSymbolAddress((void**)&pA1, g_A1);
    cudaGetSymbolAddress((void**)&pB1, g_B1);
    cudaGetSymbolAddress((void**)&pA2, g_A2);
    cudaGetSymbolAddress((void**)&pB2, g_B2);

    const int smem3 = 3 * 2 * 128 * 128;   // 98304 bytes (3 stages x 32KB)
    static int attr_done = 0;
    if (!attr_done) {
        cudaFuncSetAttribute(gemm_mma, cudaFuncAttributeMaxDynamicSharedMemorySize, smem3);
        attr_done = 1;
    }

    ln_kernel<<<BSn, 256>>>(ctx, gamma, beta);
    prep_w<<<Dn, 256>>>(Wq, Wk);
    uv_kernel<<<2 * Dn + 1, 256>>>(Wq, Wk, bq, bk);
    // GEMM1 (split-K x3, 48 chunks): partials of M = Wq @ Wk^T into g_Mp
    gemm_mma<<<dim3(Dn / 128, Dn / 128, NSPLIT), 128, smem3>>>(pA1, pB1, pMp, Dn, (size_t)Dn * Dn, KTOT / NSPLIT);
    // combine partials -> transposed hi/lo operand B2
    combine_split<<<dim3(Dn / 32, Dn / 32), dim3(32, 8)>>>();
    // GEMM2: y = x @ M  (2-term split: (xh+xl)*Mh, 32 chunks) -> fp32 g_y
    gemm_mma<<<dim3(Dn / 128, BSn / 128, 1), 128, smem3>>>(pA2, pB2, py, Dn, 0, K2TOT);
    dots_kernel<<<BSn, 256>>>();
    band_softmax<<<BSn / 256, 256>>>(eos);
    scan_kernel<<<Bn, 1024>>>(prior);
    dense_kernel<<<dim3(Sn / 256, Sn / 4, Bn), dim3(64, 4)>>>(prior, out_g, out_na);
}

// round 15
// speedup vs baseline: 1.5016x; 1.2326x over previous
#include <cuda_runtime.h>
#include <cuda_bf16.h>
#include <math.h>
#include <stdint.h>

#define Bn 4
#define Sn 2048
#define Dn 1024
#define BSn (Bn*Sn)
#define KP 2048          // physical operand pitch: [hi | lo] segments
#define KTOT 48          // logical K chunks for GEMM1 (3-term split)
#define K2TOT 16         // logical K chunks for GEMM2 (1-term: xh*Mh)
#define NSPLIT 3         // GEMM1 split-K factor

// ---------------- scratch (static device arrays; no allocation allowed) -----
__device__ float  g_x[(size_t)BSn * Dn];             // layernormed context (fp32)
__device__ float  g_y[(size_t)BSn * Dn];             // x @ M  (fp32)
__device__ __nv_bfloat16 g_A2[(size_t)BSn * KP];     // [x_hi | (unused lo)]
__device__ __nv_bfloat16 g_B2[(size_t)Dn * KP];      // [M_hi | (unused lo)] (rows = out col b)
__device__ __nv_bfloat16 g_A1[(size_t)Dn * KP];      // [Wq_hi | Wq_lo]
__device__ __nv_bfloat16 g_B1[(size_t)Dn * KP];      // [Wk_hi | Wk_lo]
__device__ float  g_Mp[NSPLIT * (size_t)Dn * Dn];    // split-K partials of M
__device__ float  g_u[Dn];                 // Wq @ bk
__device__ float  g_v[Dn];                 // Wk @ bq
__device__ float  g_c;                     // bq . bk
__device__ float  g_xu[BSn], g_xv[BSn], g_dup[BSn], g_ddn[BSn];
__device__ float  g_rvup[BSn], g_rvdn[BSn], g_rvdiag[BSn];
__device__ unsigned char g_fm[BSn];        // fully-masked row flag
__device__ double g_P[BSn];

// ======================= helpers ============================================
__device__ __forceinline__ uint32_t smem_u32(const void* p) {
    uint32_t a;
    asm("{ .reg .u64 t; cvta.to.shared.u64 t, %1; cvt.u32.u64 %0, t; }" : "=r"(a) : "l"(p));
    return a;
}
__device__ __forceinline__ void cp_async16(uint32_t dst, const void* src) {
    asm volatile("cp.async.cg.shared.global [%0], [%1], 16;" :: "r"(dst), "l"(src) : "memory");
}
__device__ __forceinline__ void cp_commit() {
    asm volatile("cp.async.commit_group;" ::: "memory");
}
__device__ __forceinline__ void cp_wait1() {
    asm volatile("cp.async.wait_group 1;" ::: "memory");
}
__device__ __forceinline__ void ldm_x4(uint32_t* r, uint32_t addr) {
    asm volatile("ldmatrix.sync.aligned.m8n8.x4.shared.b16 {%0,%1,%2,%3}, [%4];"
        : "=r"(r[0]), "=r"(r[1]), "=r"(r[2]), "=r"(r[3]) : "r"(addr));
}
__device__ __forceinline__ void mma_bf16(float* c, const uint32_t* a, uint32_t b0, uint32_t b1) {
    asm volatile("mma.sync.aligned.m16n8k16.row.col.f32.bf16.bf16.f32 "
        "{%0,%1,%2,%3}, {%4,%5,%6,%7}, {%8,%9}, {%0,%1,%2,%3};"
        : "+f"(c[0]), "+f"(c[1]), "+f"(c[2]), "+f"(c[3])
        : "r"(a[0]), "r"(a[1]), "r"(a[2]), "r"(a[3]), "r"(b0), "r"(b1));
}

// ===================== HMMA bf16 GEMM =======================================
// Logical: C[M,N] = sum over kcn K-chunks of A'[.,g] * B'[.,g]^T where
//   A' chunk g maps to physical chunk (g<32 ? g : g-32) of [hi|lo] storage,
//   B' chunk g maps to physical chunk (g<16 ? g : g-16).
// GEMM1 runs 48 chunks (3-term split: qh*kh + ql*kh + qh*kl) -> M to fp32.
// GEMM2 runs 16 chunks (1-term: xh*Mh) — measured error budget allows it
// (2-term measured 1.9e-6; dropping xl*Mh adds a comparable ~2^-9 term).
// BM=BN=128, BK=64. 128 threads = 4 warps, 64x64 warp tiles (2x2 grid).
// 3-stage cp.async pipeline, 2 CTAs/SM. blockIdx.z = K-split; out +z*zstride.
__global__ __launch_bounds__(128, 2) void gemm_mma(const __nv_bfloat16* __restrict__ A,
                                                   const __nv_bfloat16* __restrict__ Bm,
                                                   float* __restrict__ Cf,
                                                   int c_pitch, size_t zstride, int kcn) {
    constexpr int ASIZE = 128 * 128;     // 16 KB (128 rows x 128B)
    constexpr int STAGE = 2 * ASIZE;     // A + B = 32 KB
    extern __shared__ char smem[];
    uint32_t sbase = smem_u32(smem);
    int t = threadIdx.x, wid = t >> 5, lane = t & 31;
    int wm = wid & 1, wn = wid >> 1;           // 2 x 2 warp grid -> 64 x 64 tiles
    int rowBlk = blockIdx.y * 128;
    int colBlk = blockIdx.x * 128;
    int z = blockIdx.z;
    int zbase = z * kcn;

    const __nv_bfloat16* Ab = A + (size_t)rowBlk * KP;
    const __nv_bfloat16* Bb = Bm + (size_t)colBlk * KP;

    int lr = t >> 3, lj = t & 7;                       // 128 thr -> 16 rows x 8 chunks
    uint32_t sw = ((uint32_t)(lj ^ (lr & 7))) << 4;

    auto load = [&](int c, int s) {
        int g = zbase + c;
        int ga = (g < 32 ? g : g - 32) * 64;           // A physical column offset
        int gb = (g < 16 ? g : g - 16) * 64;           // B physical column offset
        uint32_t sa = sbase + (uint32_t)s * STAGE;
        #pragma unroll
        for (int i = 0; i < 8; i++) {
            int r = lr + i * 16;
            cp_async16(sa + r * 128 + sw, Ab + (size_t)r * KP + ga + lj * 8);
        }
        #pragma unroll
        for (int i = 0; i < 8; i++) {
            int r = lr + i * 16;
            cp_async16(sa + ASIZE + r * 128 + sw, Bb + (size_t)r * KP + gb + lj * 8);
        }
        cp_commit();
    };

    float acc[4][8][4];
    #pragma unroll
    for (int mt = 0; mt < 4; mt++)
        #pragma unroll
        for (int nt = 0; nt < 8; nt++)
            #pragma unroll
            for (int i = 0; i < 4; i++) acc[mt][nt][i] = 0.f;

    load(0, 0);
    load(1, 1);

    // ldmatrix lane address components
    int a_row = wm * 64 + (lane & 15);                      // + mt*16
    int a_kq  = (lane >> 4);                                // 0/1 -> +8 cols
    int b_row = wn * 64 + ((lane >> 4) << 3) + (lane & 7);  // + nt2*16
    int b_kq  = ((lane >> 3) & 1);

    for (int c = 0; c < kcn; c++) {
        cp_wait1();
        __syncthreads();
        uint32_t sa = sbase + (uint32_t)(c % 3) * STAGE;
        #pragma unroll
        for (int ks = 0; ks < 4; ks++) {
            uint32_t af[4][4];
            #pragma unroll
            for (int mt = 0; mt < 4; mt++) {
                int r = a_row + mt * 16;
                int kc = (ks * 16 + a_kq * 8) >> 3;    // 16B-column index 0..7
                ldm_x4(af[mt], sa + r * 128 + (((uint32_t)(kc ^ (r & 7))) << 4));
            }
            uint32_t bf[4][4];
            #pragma unroll
            for (int p = 0; p < 4; p++) {
                int r = b_row + p * 16;
                int kc = (ks * 16 + b_kq * 8) >> 3;
                ldm_x4(bf[p], sa + ASIZE + r * 128 + (((uint32_t)(kc ^ (r & 7))) << 4));
            }
            #pragma unroll
            for (int mt = 0; mt < 4; mt++)
                #pragma unroll
                for (int nt = 0; nt < 8; nt++)
                    mma_bf16(acc[mt][nt], af[mt], bf[nt >> 1][(nt & 1) * 2], bf[nt >> 1][(nt & 1) * 2 + 1]);
        }
        if (c + 2 < kcn) load(c + 2, (c + 2) % 3);
    }

    // ---- epilogue: fp32 store ----
    float* Cz = Cf + (size_t)z * zstride;
    int mrow0 = rowBlk + wm * 64 + (lane >> 2);
    int ncol0 = colBlk + wn * 64 + (lane & 3) * 2;
    #pragma unroll
    for (int mt = 0; mt < 4; mt++)
        #pragma unroll
        for (int nt = 0; nt < 8; nt++) {
            int r0 = mrow0 + mt * 16;
            int cc = ncol0 + nt * 8;
            *(float2*)(Cz + (size_t)r0 * c_pitch + cc)       = make_float2(acc[mt][nt][0], acc[mt][nt][1]);
            *(float2*)(Cz + (size_t)(r0 + 8) * c_pitch + cc) = make_float2(acc[mt][nt][2], acc[mt][nt][3]);
        }
}

// ---------------- combine split-K partials -> transposed hi B2 --------------
__global__ void combine_split() {
    __shared__ float tile[32][33];
    int a0 = blockIdx.y * 32, b0 = blockIdx.x * 32;
    int tx = threadIdx.x, ty = threadIdx.y;
    #pragma unroll
    for (int k = 0; k < 4; k++) {
        int a = a0 + ty + k * 8;
        size_t idx = (size_t)a * Dn + b0 + tx;
        float s = 0.f;
        #pragma unroll
        for (int z = 0; z < NSPLIT; z++) s += g_Mp[idx + (size_t)z * Dn * Dn];
        tile[ty + k * 8][tx] = s;
    }
    __syncthreads();
    #pragma unroll
    for (int k = 0; k < 4; k++) {
        int b = b0 + ty + k * 8;
        float m = tile[tx][ty + k * 8];
        __nv_bfloat16* row = g_B2 + (size_t)b * KP;
        row[a0 + tx] = __float2bfloat16(m);      // hi only; lo half never read
    }
}

// ---------------- LayerNorm (+ bf16 A operand, hi only) ---------------------
__global__ void ln_kernel(const float* __restrict__ ctx,
                          const float* __restrict__ gamma,
                          const float* __restrict__ beta) {
    __shared__ float warpred[8];
    __shared__ float stat[2];
    int r = blockIdx.x, t = threadIdx.x;
    int lane = t & 31, w = t >> 5;
    const float4* in = (const float4*)(ctx + (size_t)r * Dn);
    float4 v = in[t];

    float s = v.x + v.y + v.z + v.w;
    #pragma unroll
    for (int o = 16; o; o >>= 1) s += __shfl_xor_sync(0xffffffffu, s, o);
    if (lane == 0) warpred[w] = s;
    __syncthreads();
    if (t < 32) {
        float x = (t < 8) ? warpred[t] : 0.f;
        #pragma unroll
        for (int o = 4; o; o >>= 1) x += __shfl_xor_sync(0xffffffffu, x, o);
        if (t == 0) stat[0] = x;
    }
    __syncthreads();
    float mean = stat[0] * (1.0f / Dn);
    float dx = v.x - mean, dy = v.y - mean, dz = v.z - mean, dw = v.w - mean;
    float sq = dx*dx + dy*dy + dz*dz + dw*dw;
    __syncthreads();
    #pragma unroll
    for (int o = 16; o; o >>= 1) sq += __shfl_xor_sync(0xffffffffu, sq, o);
    if (lane == 0) warpred[w] = sq;
    __syncthreads();
    if (t < 32) {
        float x = (t < 8) ? warpred[t] : 0.f;
        #pragma unroll
        for (int o = 4; o; o >>= 1) x += __shfl_xor_sync(0xffffffffu, x, o);
        if (t == 0) stat[1] = x;
    }
    __syncthreads();
    float var = stat[1] * (1.0f / (Dn - 1));          // unbiased (Bessel)
    float rs  = 1.0f / (sqrtf(var) + 1e-6f);          // sqrt(var)+eps !
    float4 g4 = ((const float4*)gamma)[t];
    float4 b4 = ((const float4*)beta)[t];
    float4 o;
    o.x = g4.x * dx * rs + b4.x;
    o.y = g4.y * dy * rs + b4.y;
    o.z = g4.z * dz * rs + b4.z;
    o.w = g4.w * dw * rs + b4.w;
    ((float4*)(g_x + (size_t)r * Dn))[t] = o;

    // bf16 operand: hi only (lo half never read by 1-term GEMM2)
    __nv_bfloat16 hi[4];
    #pragma unroll
    for (int i = 0; i < 4; i++) hi[i] = __float2bfloat16((&o.x)[i]);
    __nv_bfloat16* row = g_A2 + (size_t)r * KP + t * 4;
    *(uint2*)(row) = *(uint2*)hi;
}

// ---------------- split Wq/Wk into bf16 operands ----------------------------
__global__ void prep_w(const float* __restrict__ Wq, const float* __restrict__ Wk) {
    int r = blockIdx.x, t = threadIdx.x;
    float4 q4 = ((const float4*)(Wq + (size_t)r * Dn))[t];
    float4 k4 = ((const float4*)(Wk + (size_t)r * Dn))[t];
    __nv_bfloat16 qh[4], ql[4], kh[4], kl[4];
    #pragma unroll
    for (int i = 0; i < 4; i++) {
        float qv = (&q4.x)[i];
        qh[i] = __float2bfloat16(qv);
        ql[i] = __float2bfloat16(qv - __bfloat162float(qh[i]));
        float kv = (&k4.x)[i];
        kh[i] = __float2bfloat16(kv);
        kl[i] = __float2bfloat16(kv - __bfloat162float(kh[i]));
    }
    __nv_bfloat16* a = g_A1 + (size_t)r * KP + t * 4;   // [Wq_hi | Wq_lo]
    *(uint2*)(a)        = *(uint2*)qh;
    *(uint2*)(a + 1024) = *(uint2*)ql;
    __nv_bfloat16* b = g_B1 + (size_t)r * KP + t * 4;   // [Wk_hi | Wk_lo]
    *(uint2*)(b)        = *(uint2*)kh;
    *(uint2*)(b + 1024) = *(uint2*)kl;
}

// ---------------- u = Wq bk, v = Wk bq, c = bq.bk ---------------------------
__global__ void uv_kernel(const float* __restrict__ Wq, const float* __restrict__ Wk,
                          const float* __restrict__ bq, const float* __restrict__ bk) {
    __shared__ float warpred[8];
    int blk = blockIdx.x, t = threadIdx.x;
    int lane = t & 31, w = t >> 5;
    float4 a, b2;
    if (blk < Dn)           { a = ((const float4*)(Wq + (size_t)blk * Dn))[t];      b2 = ((const float4*)bk)[t]; }
    else if (blk < 2 * Dn)  { a = ((const float4*)(Wk + (size_t)(blk - Dn) * Dn))[t]; b2 = ((const float4*)bq)[t]; }
    else                    { a = ((const float4*)bq)[t];                            b2 = ((const float4*)bk)[t]; }
    float s = a.x*b2.x + a.y*b2.y + a.z*b2.z + a.w*b2.w;
    #pragma unroll
    for (int o = 16; o; o >>= 1) s += __shfl_xor_sync(0xffffffffu, s, o);
    if (lane == 0) warpred[w] = s;
    __syncthreads();
    if (t == 0) {
        float tot = 0.f;
        #pragma unroll
        for (int i = 0; i < 8; i++) tot += warpred[i];
        if (blk < Dn)          g_u[blk] = tot;
        else if (blk < 2 * Dn) g_v[blk - Dn] = tot;
        else                   g_c = tot;
    }
}

// ---------------- per-row dots: y_i.x_{i+1}, y_i.x_{i-1}, x_i.u, x_i.v ------
__global__ void dots_kernel() {
    __shared__ float red[4][8];
    int r = blockIdx.x, t = threadIdx.x;
    int i = r & (Sn - 1);
    int lane = t & 31, w = t >> 5;
    float4 xr = ((const float4*)(g_x + (size_t)r * Dn))[t];
    float4 yr = ((const float4*)(g_y + (size_t)r * Dn))[t];
    float4 u4 = ((const float4*)g_u)[t];
    float4 v4 = ((const float4*)g_v)[t];
    float su = xr.x*u4.x + xr.y*u4.y + xr.z*u4.z + xr.w*u4.w;
    float sv = xr.x*v4.x + xr.y*v4.y + xr.z*v4.z + xr.w*v4.w;
    float du = 0.f, dn = 0.f;
    if (i < Sn - 1) {
        float4 xn = ((const float4*)(g_x + (size_t)(r + 1) * Dn))[t];
        du = yr.x*xn.x + yr.y*xn.y + yr.z*xn.z + yr.w*xn.w;
    }
    if (i > 0) {
        float4 xp = ((const float4*)(g_x + (size_t)(r - 1) * Dn))[t];
        dn = yr.x*xp.x + yr.y*xp.y + yr.z*xp.z + yr.w*xp.w;
    }
    float vals[4] = {su, sv, du, dn};
    #pragma unroll
    for (int k = 0; k < 4; k++) {
        float x = vals[k];
        #pragma unroll
        for (int o = 16; o; o >>= 1) x += __shfl_xor_sync(0xffffffffu, x, o);
        if (lane == 0) red[k][w] = x;
    }
    __syncthreads();
    if (t < 4) {
        float s2 = 0.f;
        #pragma unroll
        for (int w2 = 0; w2 < 8; w2++) s2 += red[t][w2];
        if      (t == 0) g_xu[r]  = s2;
        else if (t == 1) g_xv[r]  = s2;
        else if (t == 2) g_dup[r] = s2;
        else             g_ddn[r] = s2;
    }
}

// ---------------- band softmax ---------------------------------------------
__global__ void band_softmax(const int* __restrict__ eos) {
    int r = blockIdx.x * blockDim.x + threadIdx.x;
    if (r >= BSn) return;
    int b = r >> 11;
    int i = r & (Sn - 1);
    const float invD = 1.0f / Dn, invS = 1.0f / Sn;
    size_t base = ((size_t)b * Sn + i) * Sn;
    bool hu = false, hd = false;
    float su = 0.f, sd = 0.f;
    float cc = g_c;
    if (i < Sn - 1 && eos[base + i + 1] != 0) {
        hu = true;
        su = (g_dup[r] + g_xu[r] + g_xv[r + 1] + cc) * invD;
    }
    if (i > 0 && eos[base + i - 1] != 0) {
        hd = true;
        sd = (g_ddn[r] + g_xu[r] + g_xv[r - 1] + cc) * invD;
    }
    float up = 0.f, dn = 0.f, dg = 0.f;
    if (!hu && !hd) { up = invS; dn = invS; dg = invS; }     // fully-masked row -> uniform 1/S
    else if (hu && hd) {
        float m = fmaxf(su, sd);
        float eu = expf(su - m), ed = expf(sd - m);
        float inv = 1.0f / (eu + ed);
        up = eu * inv; dn = ed * inv;
    } else if (hu) up = 1.f;
    else dn = 1.f;
    g_rvup[r] = up; g_rvdn[r] = dn; g_rvdiag[r] = dg;
    g_fm[r] = (!hu && !hd) ? 1 : 0;
}

// ---------------- per-batch prefix sum of L = log(na[i][i+1]+1e-9) ----------
__global__ void scan_kernel(const float* __restrict__ prior) {
    __shared__ double sh[1024];
    int b = blockIdx.x, t = threadIdx.x;
    size_t rb = (size_t)b * Sn;

    auto Lval = [&](int i) -> double {    // i in [0, Sn-2]
        int r = b * Sn + i;
        float pr = prior[((size_t)b * Sn + i) * Sn + i + 1];
        float p = g_rvup[r] * g_rvdn[r + 1];
        float nsym = sqrtf(p + 1e-9f);
        float na = pr + (1.0f - pr) * nsym;
        return (double)logf(na + 1e-9f);
    };

    int j0 = 2 * t, j1 = 2 * t + 1;
    double a = (j0 == 0) ? 0.0 : Lval(j0 - 1);
    double c = Lval(j1 - 1);
    double pair = a + c;
    sh[t] = pair;
    __syncthreads();
    for (int off = 1; off < 1024; off <<= 1) {
        double v = sh[t];
        if (t >= off) v += sh[t - off];
        __syncthreads();
        sh[t] = v;
        __syncthreads();
    }
    double excl = sh[t] - pair;
    g_P[rb + j0] = excl + a;
    g_P[rb + j1] = excl + a + c;
}

// ---------------- dense epilogue: write na and g_attn -----------------------
// Non-band sqrt takes only 2 constant values; exp saturates to 1e-9 past |d|>38.
__global__ void dense_kernel(const float* __restrict__ prior,
                             float* __restrict__ out_g,
                             float* __restrict__ out_na) {
    const float C0 = 3.16227766e-5f;        // sqrtf(1e-9f)
    const float Cm = 4.89304178e-4f;        // sqrtf(invS^2 + 1e-9f), invS=1/2048
    int b  = blockIdx.z;
    int i  = blockIdx.y * 4 + threadIdx.y;
    int j0 = (blockIdx.x * 64 + threadIdx.x) * 4;
    size_t rb  = (size_t)b * Sn;
    size_t off = (rb + i) * Sn + j0;
    float4 pr4 = *(const float4*)(prior + off);
    double Pi = g_P[rb + i];
    double2 p01 = *(const double2*)(g_P + rb + j0);
    double2 p23 = *(const double2*)(g_P + rb + j0 + 2);
    double Pj[4] = {p01.x, p01.y, p23.x, p23.y};
    float na4[4], ga4[4];

    bool near = (j0 <= i + 1) && (j0 + 3 >= i - 1);
    if (!near) {
        unsigned char fmi = g_fm[rb + i];
        uchar4 fmj = *(const uchar4*)(g_fm + rb + j0);
        const unsigned char* fj = (const unsigned char*)&fmj;
        bool right = (j0 > i);
        #pragma unroll
        for (int jj = 0; jj < 4; jj++) {
            float pr = (&pr4.x)[jj];
            float C = (fmi && fj[jj]) ? Cm : C0;
            na4[jj] = pr + (1.0f - pr) * C;
        }
        float dlead = right ? (float)(Pj[0] - Pi) : (float)(Pi - Pj[3]);
        if (dlead <= -38.0f) {
            #pragma unroll
            for (int jj = 0; jj < 4; jj++) ga4[jj] = 1e-9f;
        } else {
            #pragma unroll
            for (int jj = 0; jj < 4; jj++) {
                float d = right ? (float)(Pj[jj] - Pi) : (float)(Pi - Pj[jj]);
                ga4[jj] = (d > -38.0f) ? (__expf(d) + 1e-9f) : 1e-9f;
            }
        }
    } else {
        float di = g_rvdiag[rb + i];
        #pragma unroll
        for (int jj = 0; jj < 4; jj++) {
            int j = j0 + jj;
            float pr = (&pr4.x)[jj];
            float p;
            if      (j == i)     p = di * di;
            else if (j == i + 1) p = g_rvup[rb + i] * g_rvdn[rb + j];
            else if (j == i - 1) p = g_rvdn[rb + i] * g_rvup[rb + j];
            else                 p = di * g_rvdiag[rb + j];
            float na = pr + (1.0f - pr) * sqrtf(p + 1e-9f);
            float ga;
            if (j == i) ga = na;
            else {
                double d = Pj[jj] - Pi;
                if (j < i) d = -d;
                ga = expf((float)d) + 1e-9f;
            }
            na4[jj] = na; ga4[jj] = ga;
        }
    }
    *(float4*)(out_na + off) = make_float4(na4[0], na4[1], na4[2], na4[3]);
    *(float4*)(out_g  + off) = make_float4(ga4[0], ga4[1], ga4[2], ga4[3]);
}

// ---------------- launch ----------------------------------------------------
extern "C" void kernel_launch(void* const* d_in, const int* in_sizes, int n_in,
                              void* d_out, int out_size) {
    const float* ctx   = (const float*)d_in[0];
    const int*   eos   = (const int*)  d_in[1];
    const float* prior = (const float*)d_in[2];
    const float* Wq    = (const float*)d_in[3];
    const float* bq    = (const float*)d_in[4];
    const float* Wk    = (const float*)d_in[5];
    const float* bk    = (const float*)d_in[6];
    const float* gamma = (const float*)d_in[7];
    const float* beta  = (const float*)d_in[8];
    float* out_g  = (float*)d_out;
    float* out_na = out_g + (size_t)Bn * Sn * Sn;

    float *py, *pMp;
    __nv_bfloat16 *pA1, *pB1, *pA2, *pB2;
    cudaGetSymbolAddress((void**)&py,  g_y);
    cudaGetSymbolAddress((void**)&pMp, g_Mp);
    cudaGetSymbolAddress((void**)&pA1, g_A1);
    cudaGetSymbolAddress((void**)&pB1, g_B1);
    cudaGetSymbolAddress((void**)&pA2, g_A2);
    cudaGetSymbolAddress((void**)&pB2, g_B2);

    const int smem3 = 3 * 2 * 128 * 128;   // 98304 bytes (3 stages x 32KB)
    static int attr_done = 0;
    if (!attr_done) {
        cudaFuncSetAttribute(gemm_mma, cudaFuncAttributeMaxDynamicSharedMemorySize, smem3);
        attr_done = 1;
    }

    ln_kernel<<<BSn, 256>>>(ctx, gamma, beta);
    prep_w<<<Dn, 256>>>(Wq, Wk);
    uv_kernel<<<2 * Dn + 1, 256>>>(Wq, Wk, bq, bk);
    // GEMM1 (split-K x3, 48 chunks): partials of M = Wq @ Wk^T into g_Mp
    gemm_mma<<<dim3(Dn / 128, Dn / 128, NSPLIT), 128, smem3>>>(pA1, pB1, pMp, Dn, (size_t)Dn * Dn, KTOT / NSPLIT);
    // combine partials -> transposed hi operand B2
    combine_split<<<dim3(Dn / 32, Dn / 32), dim3(32, 8)>>>();
    // GEMM2: y = x @ M  (1-term: xh*Mh, 16 chunks) -> fp32 g_y
    gemm_mma<<<dim3(Dn / 128, BSn / 128, 1), 128, smem3>>>(pA2, pB2, py, Dn, 0, K2TOT);
    dots_kernel<<<BSn, 256>>>();
    band_softmax<<<BSn / 256, 256>>>(eos);
    scan_kernel<<<Bn, 1024>>>(prior);
    dense_kernel<<<dim3(Sn / 256, Sn / 4, Bn), dim3(64, 4)>>>(prior, out_g, out_na);
}

// round 16
// speedup vs baseline: 1.7212x; 1.1462x over previous
#include <cuda_runtime.h>
#include <cuda_bf16.h>
#include <math.h>
#include <stdint.h>

#define Bn 4
#define Sn 2048
#define Dn 1024
#define BSn (Bn*Sn)
#define KP 2048          // physical operand pitch (bf16 elems); only hi half used now
#define K1TOT 16         // GEMM1 chunks (1-term: qh*kh)
#define K2TOT 16         // GEMM2 chunks (1-term: xh*Mh)
#define NSPLIT 2         // GEMM1 split-K factor

// ---------------- scratch (static device arrays; no allocation allowed) -----
__device__ __nv_bfloat16 g_yh[(size_t)BSn * Dn];     // y = x @ M  (bf16, dots only)
__device__ __nv_bfloat16 g_A2[(size_t)BSn * KP];     // [x_hi | unused]
__device__ __nv_bfloat16 g_B2[(size_t)Dn * KP];      // [M_hi | unused] (rows = out col b)
__device__ __nv_bfloat16 g_A1[(size_t)Dn * KP];      // [Wq_hi | unused]
__device__ __nv_bfloat16 g_B1[(size_t)Dn * KP];      // [Wk_hi | unused]
__device__ float  g_Mp[NSPLIT * (size_t)Dn * Dn];    // split-K partials of M
__device__ float  g_u[Dn];                 // Wq @ bk
__device__ float  g_v[Dn];                 // Wk @ bq
__device__ float  g_c;                     // bq . bk
__device__ float  g_xu[BSn], g_xv[BSn], g_dup[BSn], g_ddn[BSn];
__device__ float  g_rvup[BSn], g_rvdn[BSn], g_rvdiag[BSn];
__device__ unsigned char g_fm[BSn];        // fully-masked row flag
__device__ double g_P[BSn];

// ======================= helpers ============================================
__device__ __forceinline__ uint32_t smem_u32(const void* p) {
    uint32_t a;
    asm("{ .reg .u64 t; cvta.to.shared.u64 t, %1; cvt.u32.u64 %0, t; }" : "=r"(a) : "l"(p));
    return a;
}
__device__ __forceinline__ void cp_async16(uint32_t dst, const void* src) {
    asm volatile("cp.async.cg.shared.global [%0], [%1], 16;" :: "r"(dst), "l"(src) : "memory");
}
__device__ __forceinline__ void cp_commit() {
    asm volatile("cp.async.commit_group;" ::: "memory");
}
__device__ __forceinline__ void cp_wait1() {
    asm volatile("cp.async.wait_group 1;" ::: "memory");
}
__device__ __forceinline__ void ldm_x4(uint32_t* r, uint32_t addr) {
    asm volatile("ldmatrix.sync.aligned.m8n8.x4.shared.b16 {%0,%1,%2,%3}, [%4];"
        : "=r"(r[0]), "=r"(r[1]), "=r"(r[2]), "=r"(r[3]) : "r"(addr));
}
__device__ __forceinline__ void mma_bf16(float* c, const uint32_t* a, uint32_t b0, uint32_t b1) {
    asm volatile("mma.sync.aligned.m16n8k16.row.col.f32.bf16.bf16.f32 "
        "{%0,%1,%2,%3}, {%4,%5,%6,%7}, {%8,%9}, {%0,%1,%2,%3};"
        : "+f"(c[0]), "+f"(c[1]), "+f"(c[2]), "+f"(c[3])
        : "r"(a[0]), "r"(a[1]), "r"(a[2]), "r"(a[3]), "r"(b0), "r"(b1));
}
__device__ __forceinline__ uint32_t pack_bf16x2(float a, float b) {
    __nv_bfloat162 p = __floats2bfloat162_rn(a, b);
    return *reinterpret_cast<uint32_t*>(&p);
}
__device__ __forceinline__ float dot4_bf16(uint2 a, uint2 b) {
    float2 a0 = __bfloat1622float2(*reinterpret_cast<const __nv_bfloat162*>(&a.x));
    float2 a1 = __bfloat1622float2(*reinterpret_cast<const __nv_bfloat162*>(&a.y));
    float2 b0 = __bfloat1622float2(*reinterpret_cast<const __nv_bfloat162*>(&b.x));
    float2 b1 = __bfloat1622float2(*reinterpret_cast<const __nv_bfloat162*>(&b.y));
    return a0.x*b0.x + a0.y*b0.y + a1.x*b1.x + a1.y*b1.y;
}

// ===================== HMMA bf16 GEMM =======================================
// C[M,N] = sum over kcn chunks of A[.,g]*B[.,g]^T, chunks map directly into the
// hi half of the [hi|unused] operands (kcn<=16 => pure hi*hi, 1-term).
// BM=BN=128, BK=64. 128 threads = 4 warps, 64x64 warp tiles (2x2 grid).
// 3-stage cp.async pipeline, 2 CTAs/SM. blockIdx.z = K-split.
// BF16OUT=false: fp32 store to Cf + z*zstride. BF16OUT=true: bf16 store to Cb.
template <bool BF16OUT>
__global__ __launch_bounds__(128, 2) void gemm_mma(const __nv_bfloat16* __restrict__ A,
                                                   const __nv_bfloat16* __restrict__ Bm,
                                                   float* __restrict__ Cf,
                                                   __nv_bfloat16* __restrict__ Cb,
                                                   int c_pitch, size_t zstride, int kcn) {
    constexpr int ASIZE = 128 * 128;     // 16 KB (128 rows x 128B)
    constexpr int STAGE = 2 * ASIZE;     // A + B = 32 KB
    extern __shared__ char smem[];
    uint32_t sbase = smem_u32(smem);
    int t = threadIdx.x, wid = t >> 5, lane = t & 31;
    int wm = wid & 1, wn = wid >> 1;           // 2 x 2 warp grid -> 64 x 64 tiles
    int rowBlk = blockIdx.y * 128;
    int colBlk = blockIdx.x * 128;
    int z = blockIdx.z;
    int zbase = z * kcn;

    const __nv_bfloat16* Ab = A + (size_t)rowBlk * KP;
    const __nv_bfloat16* Bb = Bm + (size_t)colBlk * KP;

    int lr = t >> 3, lj = t & 7;                       // 128 thr -> 16 rows x 8 chunks
    uint32_t sw = ((uint32_t)(lj ^ (lr & 7))) << 4;

    auto load = [&](int c, int s) {
        int g = zbase + c;
        int ga = g * 64;                               // hi-half column offset
        uint32_t sa = sbase + (uint32_t)s * STAGE;
        #pragma unroll
        for (int i = 0; i < 8; i++) {
            int r = lr + i * 16;
            cp_async16(sa + r * 128 + sw, Ab + (size_t)r * KP + ga + lj * 8);
        }
        #pragma unroll
        for (int i = 0; i < 8; i++) {
            int r = lr + i * 16;
            cp_async16(sa + ASIZE + r * 128 + sw, Bb + (size_t)r * KP + ga + lj * 8);
        }
        cp_commit();
    };

    float acc[4][8][4];
    #pragma unroll
    for (int mt = 0; mt < 4; mt++)
        #pragma unroll
        for (int nt = 0; nt < 8; nt++)
            #pragma unroll
            for (int i = 0; i < 4; i++) acc[mt][nt][i] = 0.f;

    load(0, 0);
    load(1, 1);

    // ldmatrix lane address components
    int a_row = wm * 64 + (lane & 15);                      // + mt*16
    int a_kq  = (lane >> 4);                                // 0/1 -> +8 cols
    int b_row = wn * 64 + ((lane >> 4) << 3) + (lane & 7);  // + nt2*16
    int b_kq  = ((lane >> 3) & 1);

    for (int c = 0; c < kcn; c++) {
        cp_wait1();
        __syncthreads();
        uint32_t sa = sbase + (uint32_t)(c % 3) * STAGE;
        #pragma unroll
        for (int ks = 0; ks < 4; ks++) {
            uint32_t af[4][4];
            #pragma unroll
            for (int mt = 0; mt < 4; mt++) {
                int r = a_row + mt * 16;
                int kc = (ks * 16 + a_kq * 8) >> 3;    // 16B-column index 0..7
                ldm_x4(af[mt], sa + r * 128 + (((uint32_t)(kc ^ (r & 7))) << 4));
            }
            uint32_t bf[4][4];
            #pragma unroll
            for (int p = 0; p < 4; p++) {
                int r = b_row + p * 16;
                int kc = (ks * 16 + b_kq * 8) >> 3;
                ldm_x4(bf[p], sa + ASIZE + r * 128 + (((uint32_t)(kc ^ (r & 7))) << 4));
            }
            #pragma unroll
            for (int mt = 0; mt < 4; mt++)
                #pragma unroll
                for (int nt = 0; nt < 8; nt++)
                    mma_bf16(acc[mt][nt], af[mt], bf[nt >> 1][(nt & 1) * 2], bf[nt >> 1][(nt & 1) * 2 + 1]);
        }
        if (c + 2 < kcn) load(c + 2, (c + 2) % 3);
    }

    // ---- epilogue ----
    int mrow0 = rowBlk + wm * 64 + (lane >> 2);
    int ncol0 = colBlk + wn * 64 + (lane & 3) * 2;
    if (!BF16OUT) {
        float* Cz = Cf + (size_t)z * zstride;
        #pragma unroll
        for (int mt = 0; mt < 4; mt++)
            #pragma unroll
            for (int nt = 0; nt < 8; nt++) {
                int r0 = mrow0 + mt * 16;
                int cc = ncol0 + nt * 8;
                *(float2*)(Cz + (size_t)r0 * c_pitch + cc)       = make_float2(acc[mt][nt][0], acc[mt][nt][1]);
                *(float2*)(Cz + (size_t)(r0 + 8) * c_pitch + cc) = make_float2(acc[mt][nt][2], acc[mt][nt][3]);
            }
    } else {
        #pragma unroll
        for (int mt = 0; mt < 4; mt++)
            #pragma unroll
            for (int nt = 0; nt < 8; nt++) {
                int r0 = mrow0 + mt * 16;
                int cc = ncol0 + nt * 8;
                *(uint32_t*)(Cb + (size_t)r0 * c_pitch + cc)       = pack_bf16x2(acc[mt][nt][0], acc[mt][nt][1]);
                *(uint32_t*)(Cb + (size_t)(r0 + 8) * c_pitch + cc) = pack_bf16x2(acc[mt][nt][2], acc[mt][nt][3]);
            }
    }
}

// ---------------- combine split-K partials -> transposed hi B2 --------------
__global__ void combine_split() {
    __shared__ float tile[32][33];
    int a0 = blockIdx.y * 32, b0 = blockIdx.x * 32;
    int tx = threadIdx.x, ty = threadIdx.y;
    #pragma unroll
    for (int k = 0; k < 4; k++) {
        int a = a0 + ty + k * 8;
        size_t idx = (size_t)a * Dn + b0 + tx;
        float s = 0.f;
        #pragma unroll
        for (int z = 0; z < NSPLIT; z++) s += g_Mp[idx + (size_t)z * Dn * Dn];
        tile[ty + k * 8][tx] = s;
    }
    __syncthreads();
    #pragma unroll
    for (int k = 0; k < 4; k++) {
        int b = b0 + ty + k * 8;
        float m = tile[tx][ty + k * 8];
        g_B2[(size_t)b * KP + a0 + tx] = __float2bfloat16(m);
    }
}

// ---------------- LayerNorm (+ bf16 operand + x.u / x.v dots) ---------------
// NOTE: uv_kernel must run before this (reads g_u, g_v).
__global__ void ln_kernel(const float* __restrict__ ctx,
                          const float* __restrict__ gamma,
                          const float* __restrict__ beta) {
    __shared__ float warpred[8];
    __shared__ float red2[2][8];
    __shared__ float stat[2];
    int r = blockIdx.x, t = threadIdx.x;
    int lane = t & 31, w = t >> 5;
    const float4* in = (const float4*)(ctx + (size_t)r * Dn);
    float4 v = in[t];

    float s = v.x + v.y + v.z + v.w;
    #pragma unroll
    for (int o = 16; o; o >>= 1) s += __shfl_xor_sync(0xffffffffu, s, o);
    if (lane == 0) warpred[w] = s;
    __syncthreads();
    if (t < 32) {
        float x = (t < 8) ? warpred[t] : 0.f;
        #pragma unroll
        for (int o = 4; o; o >>= 1) x += __shfl_xor_sync(0xffffffffu, x, o);
        if (t == 0) stat[0] = x;
    }
    __syncthreads();
    float mean = stat[0] * (1.0f / Dn);
    float dx = v.x - mean, dy = v.y - mean, dz = v.z - mean, dw = v.w - mean;
    float sq = dx*dx + dy*dy + dz*dz + dw*dw;
    __syncthreads();
    #pragma unroll
    for (int o = 16; o; o >>= 1) sq += __shfl_xor_sync(0xffffffffu, sq, o);
    if (lane == 0) warpred[w] = sq;
    __syncthreads();
    if (t < 32) {
        float x = (t < 8) ? warpred[t] : 0.f;
        #pragma unroll
        for (int o = 4; o; o >>= 1) x += __shfl_xor_sync(0xffffffffu, x, o);
        if (t == 0) stat[1] = x;
    }
    __syncthreads();
    float var = stat[1] * (1.0f / (Dn - 1));          // unbiased (Bessel)
    float rs  = 1.0f / (sqrtf(var) + 1e-6f);          // sqrt(var)+eps !
    float4 g4 = ((const float4*)gamma)[t];
    float4 b4 = ((const float4*)beta)[t];
    float4 o;
    o.x = g4.x * dx * rs + b4.x;
    o.y = g4.y * dy * rs + b4.y;
    o.z = g4.z * dz * rs + b4.z;
    o.w = g4.w * dw * rs + b4.w;

    // x.u and x.v row dots (exact fp32 x from registers)
    float4 u4 = ((const float4*)g_u)[t];
    float4 v4 = ((const float4*)g_v)[t];
    float su = o.x*u4.x + o.y*u4.y + o.z*u4.z + o.w*u4.w;
    float sv = o.x*v4.x + o.y*v4.y + o.z*v4.z + o.w*v4.w;
    #pragma unroll
    for (int of = 16; of; of >>= 1) {
        su += __shfl_xor_sync(0xffffffffu, su, of);
        sv += __shfl_xor_sync(0xffffffffu, sv, of);
    }
    if (lane == 0) { red2[0][w] = su; red2[1][w] = sv; }

    // bf16 operand: hi only
    __nv_bfloat16 hi[4];
    #pragma unroll
    for (int i = 0; i < 4; i++) hi[i] = __float2bfloat16((&o.x)[i]);
    *(uint2*)(g_A2 + (size_t)r * KP + t * 4) = *(uint2*)hi;

    __syncthreads();
    if (t < 2) {
        float tot = 0.f;
        #pragma unroll
        for (int i = 0; i < 8; i++) tot += red2[t][i];
        if (t == 0) g_xu[r] = tot; else g_xv[r] = tot;
    }
}

// ---------------- Wq/Wk -> bf16 hi operands ---------------------------------
__global__ void prep_w(const float* __restrict__ Wq, const float* __restrict__ Wk) {
    int r = blockIdx.x, t = threadIdx.x;
    float4 q4 = ((const float4*)(Wq + (size_t)r * Dn))[t];
    float4 k4 = ((const float4*)(Wk + (size_t)r * Dn))[t];
    __nv_bfloat16 qh[4], kh[4];
    #pragma unroll
    for (int i = 0; i < 4; i++) {
        qh[i] = __float2bfloat16((&q4.x)[i]);
        kh[i] = __float2bfloat16((&k4.x)[i]);
    }
    *(uint2*)(g_A1 + (size_t)r * KP + t * 4) = *(uint2*)qh;
    *(uint2*)(g_B1 + (size_t)r * KP + t * 4) = *(uint2*)kh;
}

// ---------------- u = Wq bk, v = Wk bq, c = bq.bk ---------------------------
__global__ void uv_kernel(const float* __restrict__ Wq, const float* __restrict__ Wk,
                          const float* __restrict__ bq, const float* __restrict__ bk) {
    __shared__ float warpred[8];
    int blk = blockIdx.x, t = threadIdx.x;
    int lane = t & 31, w = t >> 5;
    float4 a, b2;
    if (blk < Dn)           { a = ((const float4*)(Wq + (size_t)blk * Dn))[t];      b2 = ((const float4*)bk)[t]; }
    else if (blk < 2 * Dn)  { a = ((const float4*)(Wk + (size_t)(blk - Dn) * Dn))[t]; b2 = ((const float4*)bq)[t]; }
    else                    { a = ((const float4*)bq)[t];                            b2 = ((const float4*)bk)[t]; }
    float s = a.x*b2.x + a.y*b2.y + a.z*b2.z + a.w*b2.w;
    #pragma unroll
    for (int o = 16; o; o >>= 1) s += __shfl_xor_sync(0xffffffffu, s, o);
    if (lane == 0) warpred[w] = s;
    __syncthreads();
    if (t == 0) {
        float tot = 0.f;
        #pragma unroll
        for (int i = 0; i < 8; i++) tot += warpred[i];
        if (blk < Dn)          g_u[blk] = tot;
        else if (blk < 2 * Dn) g_v[blk - Dn] = tot;
        else                   g_c = tot;
    }
}

// ---------------- per-row band dots: y_i.x_{i+1}, y_i.x_{i-1} (bf16) --------
__global__ void dots_kernel() {
    __shared__ float red[2][8];
    int r = blockIdx.x, t = threadIdx.x;
    int i = r & (Sn - 1);
    int lane = t & 31, w = t >> 5;
    uint2 yu = *(const uint2*)(g_yh + (size_t)r * Dn + t * 4);
    float du = 0.f, dn = 0.f;
    if (i < Sn - 1) {
        uint2 xn = *(const uint2*)(g_A2 + (size_t)(r + 1) * KP + t * 4);
        du = dot4_bf16(yu, xn);
    }
    if (i > 0) {
        uint2 xp = *(const uint2*)(g_A2 + (size_t)(r - 1) * KP + t * 4);
        dn = dot4_bf16(yu, xp);
    }
    #pragma unroll
    for (int o = 16; o; o >>= 1) {
        du += __shfl_xor_sync(0xffffffffu, du, o);
        dn += __shfl_xor_sync(0xffffffffu, dn, o);
    }
    if (lane == 0) { red[0][w] = du; red[1][w] = dn; }
    __syncthreads();
    if (t < 2) {
        float s2 = 0.f;
        #pragma unroll
        for (int w2 = 0; w2 < 8; w2++) s2 += red[t][w2];
        if (t == 0) g_dup[r] = s2; else g_ddn[r] = s2;
    }
}

// ---------------- band softmax ---------------------------------------------
__global__ void band_softmax(const int* __restrict__ eos) {
    int r = blockIdx.x * blockDim.x + threadIdx.x;
    if (r >= BSn) return;
    int b = r >> 11;
    int i = r & (Sn - 1);
    const float invD = 1.0f / Dn, invS = 1.0f / Sn;
    size_t base = ((size_t)b * Sn + i) * Sn;
    bool hu = false, hd = false;
    float su = 0.f, sd = 0.f;
    float cc = g_c;
    if (i < Sn - 1 && eos[base + i + 1] != 0) {
        hu = true;
        su = (g_dup[r] + g_xu[r] + g_xv[r + 1] + cc) * invD;
    }
    if (i > 0 && eos[base + i - 1] != 0) {
        hd = true;
        sd = (g_ddn[r] + g_xu[r] + g_xv[r - 1] + cc) * invD;
    }
    float up = 0.f, dn = 0.f, dg = 0.f;
    if (!hu && !hd) { up = invS; dn = invS; dg = invS; }     // fully-masked row -> uniform 1/S
    else if (hu && hd) {
        float m = fmaxf(su, sd);
        float eu = expf(su - m), ed = expf(sd - m);
        float inv = 1.0f / (eu + ed);
        up = eu * inv; dn = ed * inv;
    } else if (hu) up = 1.f;
    else dn = 1.f;
    g_rvup[r] = up; g_rvdn[r] = dn; g_rvdiag[r] = dg;
    g_fm[r] = (!hu && !hd) ? 1 : 0;
}

// ---------------- per-batch prefix sum of L = log(na[i][i+1]+1e-9) ----------
__global__ void scan_kernel(const float* __restrict__ prior) {
    __shared__ double sh[1024];
    int b = blockIdx.x, t = threadIdx.x;
    size_t rb = (size_t)b * Sn;

    auto Lval = [&](int i) -> double {    // i in [0, Sn-2]
        int r = b * Sn + i;
        float pr = prior[((size_t)b * Sn + i) * Sn + i + 1];
        float p = g_rvup[r] * g_rvdn[r + 1];
        float nsym = sqrtf(p + 1e-9f);
        float na = pr + (1.0f - pr) * nsym;
        return (double)logf(na + 1e-9f);
    };

    int j0 = 2 * t, j1 = 2 * t + 1;
    double a = (j0 == 0) ? 0.0 : Lval(j0 - 1);
    double c = Lval(j1 - 1);
    double pair = a + c;
    sh[t] = pair;
    __syncthreads();
    for (int off = 1; off < 1024; off <<= 1) {
        double v = sh[t];
        if (t >= off) v += sh[t - off];
        __syncthreads();
        sh[t] = v;
        __syncthreads();
    }
    double excl = sh[t] - pair;
    g_P[rb + j0] = excl + a;
    g_P[rb + j1] = excl + a + c;
}

// ---------------- dense epilogue: write na and g_attn -----------------------
// Non-band sqrt takes only 2 constant values; exp saturates to 1e-9 past |d|>38.
__global__ void dense_kernel(const float* __restrict__ prior,
                             float* __restrict__ out_g,
                             float* __restrict__ out_na) {
    const float C0 = 3.16227766e-5f;        // sqrtf(1e-9f)
    const float Cm = 4.89304178e-4f;        // sqrtf(invS^2 + 1e-9f), invS=1/2048
    int b  = blockIdx.z;
    int i  = blockIdx.y * 4 + threadIdx.y;
    int j0 = (blockIdx.x * 64 + threadIdx.x) * 4;
    size_t rb  = (size_t)b * Sn;
    size_t off = (rb + i) * Sn + j0;
    float4 pr4 = *(const float4*)(prior + off);
    double Pi = g_P[rb + i];
    double2 p01 = *(const double2*)(g_P + rb + j0);
    double2 p23 = *(const double2*)(g_P + rb + j0 + 2);
    double Pj[4] = {p01.x, p01.y, p23.x, p23.y};
    float na4[4], ga4[4];

    bool near = (j0 <= i + 1) && (j0 + 3 >= i - 1);
    if (!near) {
        unsigned char fmi = g_fm[rb + i];
        uchar4 fmj = *(const uchar4*)(g_fm + rb + j0);
        const unsigned char* fj = (const unsigned char*)&fmj;
        bool right = (j0 > i);
        #pragma unroll
        for (int jj = 0; jj < 4; jj++) {
            float pr = (&pr4.x)[jj];
            float C = (fmi && fj[jj]) ? Cm : C0;
            na4[jj] = pr + (1.0f - pr) * C;
        }
        float dlead = right ? (float)(Pj[0] - Pi) : (float)(Pi - Pj[3]);
        if (dlead <= -38.0f) {
            #pragma unroll
            for (int jj = 0; jj < 4; jj++) ga4[jj] = 1e-9f;
        } else {
            #pragma unroll
            for (int jj = 0; jj < 4; jj++) {
                float d = right ? (float)(Pj[jj] - Pi) : (float)(Pi - Pj[jj]);
                ga4[jj] = (d > -38.0f) ? (__expf(d) + 1e-9f) : 1e-9f;
            }
        }
    } else {
        float di = g_rvdiag[rb + i];
        #pragma unroll
        for (int jj = 0; jj < 4; jj++) {
            int j = j0 + jj;
            float pr = (&pr4.x)[jj];
            float p;
            if      (j == i)     p = di * di;
            else if (j == i + 1) p = g_rvup[rb + i] * g_rvdn[rb + j];
            else if (j == i - 1) p = g_rvdn[rb + i] * g_rvup[rb + j];
            else                 p = di * g_rvdiag[rb + j];
            float na = pr + (1.0f - pr) * sqrtf(p + 1e-9f);
            float ga;
            if (j == i) ga = na;
            else {
                double d = Pj[jj] - Pi;
                if (j < i) d = -d;
                ga = expf((float)d) + 1e-9f;
            }
            na4[jj] = na; ga4[jj] = ga;
        }
    }
    *(float4*)(out_na + off) = make_float4(na4[0], na4[1], na4[2], na4[3]);
    *(float4*)(out_g  + off) = make_float4(ga4[0], ga4[1], ga4[2], ga4[3]);
}

// ---------------- launch ----------------------------------------------------
extern "C" void kernel_launch(void* const* d_in, const int* in_sizes, int n_in,
                              void* d_out, int out_size) {
    const float* ctx   = (const float*)d_in[0];
    const int*   eos   = (const int*)  d_in[1];
    const float* prior = (const float*)d_in[2];
    const float* Wq    = (const float*)d_in[3];
    const float* bq    = (const float*)d_in[4];
    const float* Wk    = (const float*)d_in[5];
    const float* bk    = (const float*)d_in[6];
    const float* gamma = (const float*)d_in[7];
    const float* beta  = (const float*)d_in[8];
    float* out_g  = (float*)d_out;
    float* out_na = out_g + (size_t)Bn * Sn * Sn;

    float *pMp;
    __nv_bfloat16 *pA1, *pB1, *pA2, *pB2, *pYh;
    cudaGetSymbolAddress((void**)&pMp, g_Mp);
    cudaGetSymbolAddress((void**)&pA1, g_A1);
    cudaGetSymbolAddress((void**)&pB1, g_B1);
    cudaGetSymbolAddress((void**)&pA2, g_A2);
    cudaGetSymbolAddress((void**)&pB2, g_B2);
    cudaGetSymbolAddress((void**)&pYh, g_yh);

    const int smem3 = 3 * 2 * 128 * 128;   // 98304 bytes (3 stages x 32KB)
    static int attr_done = 0;
    if (!attr_done) {
        cudaFuncSetAttribute(gemm_mma<false>, cudaFuncAttributeMaxDynamicSharedMemorySize, smem3);
        cudaFuncSetAttribute(gemm_mma<true>,  cudaFuncAttributeMaxDynamicSharedMemorySize, smem3);
        attr_done = 1;
    }

    uv_kernel<<<2 * Dn + 1, 256>>>(Wq, Wk, bq, bk);
    prep_w<<<Dn, 256>>>(Wq, Wk);
    ln_kernel<<<BSn, 256>>>(ctx, gamma, beta);
    // GEMM1 (1-term, split-K x2): partials of M = Wq @ Wk^T into g_Mp
    gemm_mma<false><<<dim3(Dn / 128, Dn / 128, NSPLIT), 128, smem3>>>(pA1, pB1, pMp, nullptr, Dn, (size_t)Dn * Dn, K1TOT / NSPLIT);
    // combine partials -> transposed hi operand B2
    combine_split<<<dim3(Dn / 32, Dn / 32), dim3(32, 8)>>>();
    // GEMM2: y = x @ M  (1-term: xh*Mh, 16 chunks) -> bf16 g_yh
    gemm_mma<true><<<dim3(Dn / 128, BSn / 128, 1), 128, smem3>>>(pA2, pB2, nullptr, pYh, Dn, 0, K2TOT);
    dots_kernel<<<BSn, 256>>>();
    band_softmax<<<BSn / 256, 256>>>(eos);
    scan_kernel<<<Bn, 1024>>>(prior);
    dense_kernel<<<dim3(Sn / 256, Sn / 4, Bn), dim3(64, 4)>>>(prior, out_g, out_na);
}

// round 17
// speedup vs baseline: 1.7683x; 1.0274x over previous
#include <cuda_runtime.h>
#include <cuda_bf16.h>
#include <math.h>
#include <stdint.h>

#define Bn 4
#define Sn 2048
#define Dn 1024
#define BSn (Bn*Sn)
#define KP 1024          // operand pitch (bf16 elems) — tight, hi only
#define K1TOT 16         // GEMM1 chunks (1-term: qh*kh)
#define K2TOT 16         // GEMM2 chunks (1-term: xh*Mh)
#define NSPLIT 2         // GEMM1 split-K factor

// ---------------- scratch (static device arrays; no allocation allowed) -----
__device__ __nv_bfloat16 g_yh[(size_t)BSn * Dn];     // y = x @ M  (bf16, dots only)
__device__ __nv_bfloat16 g_A2[(size_t)BSn * KP];     // x_hi
__device__ __nv_bfloat16 g_B2[(size_t)Dn * KP];      // M_hi (rows = out col b)
__device__ __nv_bfloat16 g_A1[(size_t)Dn * KP];      // Wq_hi
__device__ __nv_bfloat16 g_B1[(size_t)Dn * KP];      // Wk_hi
__device__ float  g_Mp[NSPLIT * (size_t)Dn * Dn];    // split-K partials of M
__device__ float  g_u[Dn];                 // Wq @ bk
__device__ float  g_v[Dn];                 // Wk @ bq
__device__ float  g_c;                     // bq . bk
__device__ float  g_xu[BSn], g_xv[BSn], g_dup[BSn], g_ddn[BSn];
__device__ float  g_rvup[BSn], g_rvdn[BSn], g_rvdiag[BSn];
__device__ unsigned char g_fm[BSn];        // fully-masked row flag
__device__ double g_P[BSn];

// ======================= helpers ============================================
__device__ __forceinline__ uint32_t smem_u32(const void* p) {
    uint32_t a;
    asm("{ .reg .u64 t; cvta.to.shared.u64 t, %1; cvt.u32.u64 %0, t; }" : "=r"(a) : "l"(p));
    return a;
}
__device__ __forceinline__ void cp_async16(uint32_t dst, const void* src) {
    asm volatile("cp.async.cg.shared.global [%0], [%1], 16;" :: "r"(dst), "l"(src) : "memory");
}
__device__ __forceinline__ void cp_commit() {
    asm volatile("cp.async.commit_group;" ::: "memory");
}
__device__ __forceinline__ void cp_wait1() {
    asm volatile("cp.async.wait_group 1;" ::: "memory");
}
__device__ __forceinline__ void ldm_x4(uint32_t* r, uint32_t addr) {
    asm volatile("ldmatrix.sync.aligned.m8n8.x4.shared.b16 {%0,%1,%2,%3}, [%4];"
        : "=r"(r[0]), "=r"(r[1]), "=r"(r[2]), "=r"(r[3]) : "r"(addr));
}
__device__ __forceinline__ void mma_bf16(float* c, const uint32_t* a, uint32_t b0, uint32_t b1) {
    asm volatile("mma.sync.aligned.m16n8k16.row.col.f32.bf16.bf16.f32 "
        "{%0,%1,%2,%3}, {%4,%5,%6,%7}, {%8,%9}, {%0,%1,%2,%3};"
        : "+f"(c[0]), "+f"(c[1]), "+f"(c[2]), "+f"(c[3])
        : "r"(a[0]), "r"(a[1]), "r"(a[2]), "r"(a[3]), "r"(b0), "r"(b1));
}
__device__ __forceinline__ uint32_t pack_bf16x2(float a, float b) {
    __nv_bfloat162 p = __floats2bfloat162_rn(a, b);
    return *reinterpret_cast<uint32_t*>(&p);
}
__device__ __forceinline__ float dot8_bf16(uint4 a, uint4 b) {
    const uint32_t* pa = &a.x;
    const uint32_t* pb = &b.x;
    float s = 0.f;
    #pragma unroll
    for (int i = 0; i < 4; i++) {
        float2 fa = __bfloat1622float2(*reinterpret_cast<const __nv_bfloat162*>(&pa[i]));
        float2 fb = __bfloat1622float2(*reinterpret_cast<const __nv_bfloat162*>(&pb[i]));
        s += fa.x * fb.x + fa.y * fb.y;
    }
    return s;
}

// ===================== HMMA bf16 GEMM =======================================
// C[M,N] = A[M,1024] * B[N,1024]^T over kcn 64-wide chunks (bf16, fp32 acc).
// BM=BN=128, BK=64. 128 threads = 4 warps, 64x64 warp tiles (2x2 grid).
// 3-stage cp.async pipeline, 2 CTAs/SM. blockIdx.z = K-split.
// BF16OUT=false: fp32 store to Cf + z*zstride. BF16OUT=true: bf16 store to Cb.
template <bool BF16OUT>
__global__ __launch_bounds__(128, 2) void gemm_mma(const __nv_bfloat16* __restrict__ A,
                                                   const __nv_bfloat16* __restrict__ Bm,
                                                   float* __restrict__ Cf,
                                                   __nv_bfloat16* __restrict__ Cb,
                                                   int c_pitch, size_t zstride, int kcn) {
    constexpr int ASIZE = 128 * 128;     // 16 KB (128 rows x 128B)
    constexpr int STAGE = 2 * ASIZE;     // A + B = 32 KB
    extern __shared__ char smem[];
    uint32_t sbase = smem_u32(smem);
    int t = threadIdx.x, wid = t >> 5, lane = t & 31;
    int wm = wid & 1, wn = wid >> 1;           // 2 x 2 warp grid -> 64 x 64 tiles
    int rowBlk = blockIdx.y * 128;
    int colBlk = blockIdx.x * 128;
    int z = blockIdx.z;
    int zbase = z * kcn;

    const __nv_bfloat16* Ab = A + (size_t)rowBlk * KP;
    const __nv_bfloat16* Bb = Bm + (size_t)colBlk * KP;

    int lr = t >> 3, lj = t & 7;                       // 128 thr -> 16 rows x 8 chunks
    uint32_t sw = ((uint32_t)(lj ^ (lr & 7))) << 4;

    auto load = [&](int c, int s) {
        int ga = (zbase + c) * 64;
        uint32_t sa = sbase + (uint32_t)s * STAGE;
        #pragma unroll
        for (int i = 0; i < 8; i++) {
            int r = lr + i * 16;
            cp_async16(sa + r * 128 + sw, Ab + (size_t)r * KP + ga + lj * 8);
        }
        #pragma unroll
        for (int i = 0; i < 8; i++) {
            int r = lr + i * 16;
            cp_async16(sa + ASIZE + r * 128 + sw, Bb + (size_t)r * KP + ga + lj * 8);
        }
        cp_commit();
    };

    float acc[4][8][4];
    #pragma unroll
    for (int mt = 0; mt < 4; mt++)
        #pragma unroll
        for (int nt = 0; nt < 8; nt++)
            #pragma unroll
            for (int i = 0; i < 4; i++) acc[mt][nt][i] = 0.f;

    load(0, 0);
    load(1, 1);

    // ldmatrix lane address components
    int a_row = wm * 64 + (lane & 15);                      // + mt*16
    int a_kq  = (lane >> 4);                                // 0/1 -> +8 cols
    int b_row = wn * 64 + ((lane >> 4) << 3) + (lane & 7);  // + nt2*16
    int b_kq  = ((lane >> 3) & 1);

    for (int c = 0; c < kcn; c++) {
        cp_wait1();
        __syncthreads();
        uint32_t sa = sbase + (uint32_t)(c % 3) * STAGE;
        #pragma unroll
        for (int ks = 0; ks < 4; ks++) {
            uint32_t af[4][4];
            #pragma unroll
            for (int mt = 0; mt < 4; mt++) {
                int r = a_row + mt * 16;
                int kc = (ks * 16 + a_kq * 8) >> 3;    // 16B-column index 0..7
                ldm_x4(af[mt], sa + r * 128 + (((uint32_t)(kc ^ (r & 7))) << 4));
            }
            uint32_t bf[4][4];
            #pragma unroll
            for (int p = 0; p < 4; p++) {
                int r = b_row + p * 16;
                int kc = (ks * 16 + b_kq * 8) >> 3;
                ldm_x4(bf[p], sa + ASIZE + r * 128 + (((uint32_t)(kc ^ (r & 7))) << 4));
            }
            #pragma unroll
            for (int mt = 0; mt < 4; mt++)
                #pragma unroll
                for (int nt = 0; nt < 8; nt++)
                    mma_bf16(acc[mt][nt], af[mt], bf[nt >> 1][(nt & 1) * 2], bf[nt >> 1][(nt & 1) * 2 + 1]);
        }
        if (c + 2 < kcn) load(c + 2, (c + 2) % 3);
    }

    // ---- epilogue ----
    int mrow0 = rowBlk + wm * 64 + (lane >> 2);
    int ncol0 = colBlk + wn * 64 + (lane & 3) * 2;
    if (!BF16OUT) {
        float* Cz = Cf + (size_t)z * zstride;
        #pragma unroll
        for (int mt = 0; mt < 4; mt++)
            #pragma unroll
            for (int nt = 0; nt < 8; nt++) {
                int r0 = mrow0 + mt * 16;
                int cc = ncol0 + nt * 8;
                *(float2*)(Cz + (size_t)r0 * c_pitch + cc)       = make_float2(acc[mt][nt][0], acc[mt][nt][1]);
                *(float2*)(Cz + (size_t)(r0 + 8) * c_pitch + cc) = make_float2(acc[mt][nt][2], acc[mt][nt][3]);
            }
    } else {
        #pragma unroll
        for (int mt = 0; mt < 4; mt++)
            #pragma unroll
            for (int nt = 0; nt < 8; nt++) {
                int r0 = mrow0 + mt * 16;
                int cc = ncol0 + nt * 8;
                *(uint32_t*)(Cb + (size_t)r0 * c_pitch + cc)       = pack_bf16x2(acc[mt][nt][0], acc[mt][nt][1]);
                *(uint32_t*)(Cb + (size_t)(r0 + 8) * c_pitch + cc) = pack_bf16x2(acc[mt][nt][2], acc[mt][nt][3]);
            }
    }
}

// ---------------- combine split-K partials -> transposed hi B2 --------------
__global__ void combine_split() {
    __shared__ float tile[32][33];
    int a0 = blockIdx.y * 32, b0 = blockIdx.x * 32;
    int tx = threadIdx.x, ty = threadIdx.y;
    #pragma unroll
    for (int k = 0; k < 4; k++) {
        int a = a0 + ty + k * 8;
        size_t idx = (size_t)a * Dn + b0 + tx;
        float s = 0.f;
        #pragma unroll
        for (int z = 0; z < NSPLIT; z++) s += g_Mp[idx + (size_t)z * Dn * Dn];
        tile[ty + k * 8][tx] = s;
    }
    __syncthreads();
    #pragma unroll
    for (int k = 0; k < 4; k++) {
        int b = b0 + ty + k * 8;
        g_B2[(size_t)b * KP + a0 + tx] = __float2bfloat16(tile[tx][ty + k * 8]);
    }
}

// ---------------- prep: W operands + u/v/c ----------------------------------
// blk < Dn: row of Wq -> qh operand + dot with bk (u)
// blk < 2Dn: row of Wk -> kh operand + dot with bq (v)
// blk == 2Dn: bq.bk
__global__ void prep_kernel(const float* __restrict__ Wq, const float* __restrict__ Wk,
                            const float* __restrict__ bq, const float* __restrict__ bk) {
    __shared__ float warpred[8];
    int blk = blockIdx.x, t = threadIdx.x;
    int lane = t & 31, w = t >> 5;
    float4 a, b2;
    if (blk < Dn)           { a = ((const float4*)(Wq + (size_t)blk * Dn))[t];        b2 = ((const float4*)bk)[t]; }
    else if (blk < 2 * Dn)  { a = ((const float4*)(Wk + (size_t)(blk - Dn) * Dn))[t]; b2 = ((const float4*)bq)[t]; }
    else                    { a = ((const float4*)bq)[t];                              b2 = ((const float4*)bk)[t]; }

    if (blk < 2 * Dn) {
        __nv_bfloat16 h[4];
        #pragma unroll
        for (int i = 0; i < 4; i++) h[i] = __float2bfloat16((&a.x)[i]);
        __nv_bfloat16* dst = (blk < Dn) ? (g_A1 + (size_t)blk * KP) : (g_B1 + (size_t)(blk - Dn) * KP);
        *(uint2*)(dst + t * 4) = *(uint2*)h;
    }

    float s = a.x*b2.x + a.y*b2.y + a.z*b2.z + a.w*b2.w;
    #pragma unroll
    for (int o = 16; o; o >>= 1) s += __shfl_xor_sync(0xffffffffu, s, o);
    if (lane == 0) warpred[w] = s;
    __syncthreads();
    if (t == 0) {
        float tot = 0.f;
        #pragma unroll
        for (int i = 0; i < 8; i++) tot += warpred[i];
        if (blk < Dn)          g_u[blk] = tot;
        else if (blk < 2 * Dn) g_v[blk - Dn] = tot;
        else                   g_c = tot;
    }
}

// ---------------- LayerNorm (+ bf16 operand + x.u / x.v dots) ---------------
// NOTE: prep_kernel must run before this (reads g_u, g_v).
__global__ void ln_kernel(const float* __restrict__ ctx,
                          const float* __restrict__ gamma,
                          const float* __restrict__ beta) {
    __shared__ float warpred[8];
    __shared__ float red2[2][8];
    __shared__ float stat[2];
    int r = blockIdx.x, t = threadIdx.x;
    int lane = t & 31, w = t >> 5;
    const float4* in = (const float4*)(ctx + (size_t)r * Dn);
    float4 v = in[t];

    float s = v.x + v.y + v.z + v.w;
    #pragma unroll
    for (int o = 16; o; o >>= 1) s += __shfl_xor_sync(0xffffffffu, s, o);
    if (lane == 0) warpred[w] = s;
    __syncthreads();
    if (t < 32) {
        float x = (t < 8) ? warpred[t] : 0.f;
        #pragma unroll
        for (int o = 4; o; o >>= 1) x += __shfl_xor_sync(0xffffffffu, x, o);
        if (t == 0) stat[0] = x;
    }
    __syncthreads();
    float mean = stat[0] * (1.0f / Dn);
    float dx = v.x - mean, dy = v.y - mean, dz = v.z - mean, dw = v.w - mean;
    float sq = dx*dx + dy*dy + dz*dz + dw*dw;
    __syncthreads();
    #pragma unroll
    for (int o = 16; o; o >>= 1) sq += __shfl_xor_sync(0xffffffffu, sq, o);
    if (lane == 0) warpred[w] = sq;
    __syncthreads();
    if (t < 32) {
        float x = (t < 8) ? warpred[t] : 0.f;
        #pragma unroll
        for (int o = 4; o; o >>= 1) x += __shfl_xor_sync(0xffffffffu, x, o);
        if (t == 0) stat[1] = x;
    }
    __syncthreads();
    float var = stat[1] * (1.0f / (Dn - 1));          // unbiased (Bessel)
    float rs  = 1.0f / (sqrtf(var) + 1e-6f);          // sqrt(var)+eps !
    float4 g4 = ((const float4*)gamma)[t];
    float4 b4 = ((const float4*)beta)[t];
    float4 o;
    o.x = g4.x * dx * rs + b4.x;
    o.y = g4.y * dy * rs + b4.y;
    o.z = g4.z * dz * rs + b4.z;
    o.w = g4.w * dw * rs + b4.w;

    // x.u and x.v row dots (exact fp32 x from registers)
    float4 u4 = ((const float4*)g_u)[t];
    float4 v4 = ((const float4*)g_v)[t];
    float su = o.x*u4.x + o.y*u4.y + o.z*u4.z + o.w*u4.w;
    float sv = o.x*v4.x + o.y*v4.y + o.z*v4.z + o.w*v4.w;
    #pragma unroll
    for (int of = 16; of; of >>= 1) {
        su += __shfl_xor_sync(0xffffffffu, su, of);
        sv += __shfl_xor_sync(0xffffffffu, sv, of);
    }
    if (lane == 0) { red2[0][w] = su; red2[1][w] = sv; }

    __nv_bfloat16 hi[4];
    #pragma unroll
    for (int i = 0; i < 4; i++) hi[i] = __float2bfloat16((&o.x)[i]);
    *(uint2*)(g_A2 + (size_t)r * KP + t * 4) = *(uint2*)hi;

    __syncthreads();
    if (t < 2) {
        float tot = 0.f;
        #pragma unroll
        for (int i = 0; i < 8; i++) tot += red2[t][i];
        if (t == 0) g_xu[r] = tot; else g_xv[r] = tot;
    }
}

// ---------------- per-row band dots: 2 rows/CTA, uint4 loads ----------------
__global__ void dots_kernel() {
    __shared__ float red[2][2][4];
    int t = threadIdx.x;
    int half = t >> 7, ht = t & 127;
    int r = blockIdx.x * 2 + half;
    int i = r & (Sn - 1);
    int lane = ht & 31, w = ht >> 5;       // w in 0..3
    uint4 yu = *(const uint4*)(g_yh + (size_t)r * Dn + ht * 8);
    float du = 0.f, dn = 0.f;
    if (i < Sn - 1) {
        uint4 xn = *(const uint4*)(g_A2 + (size_t)(r + 1) * KP + ht * 8);
        du = dot8_bf16(yu, xn);
    }
    if (i > 0) {
        uint4 xp = *(const uint4*)(g_A2 + (size_t)(r - 1) * KP + ht * 8);
        dn = dot8_bf16(yu, xp);
    }
    #pragma unroll
    for (int o = 16; o; o >>= 1) {
        du += __shfl_xor_sync(0xffffffffu, du, o);
        dn += __shfl_xor_sync(0xffffffffu, dn, o);
    }
    if (lane == 0) { red[half][0][w] = du; red[half][1][w] = dn; }
    __syncthreads();
    if (ht < 2) {
        float s2 = 0.f;
        #pragma unroll
        for (int w2 = 0; w2 < 4; w2++) s2 += red[half][ht][w2];
        if (ht == 0) g_dup[r] = s2; else g_ddn[r] = s2;
    }
}

// ---------------- fused band softmax + per-batch prefix scan ----------------
// One CTA per batch, 1024 threads; each thread owns rows 2t, 2t+1.
// Phase 1: band softmax -> shared s_up/s_dn (+ gmem rv/fm for dense).
// Phase 2: inclusive scan of L = log(na[i][i+1]+1e-9) -> g_P.
__global__ void scan_softmax(const int* __restrict__ eos,
                             const float* __restrict__ prior) {
    __shared__ double sh[1024];
    __shared__ float s_up[Sn], s_dn[Sn];
    int b = blockIdx.x, t = threadIdx.x;
    size_t rb = (size_t)b * Sn;
    const float invD = 1.0f / Dn, invS = 1.0f / Sn;

    #pragma unroll
    for (int k = 0; k < 2; k++) {
        int i = 2 * t + k;
        int r = b * Sn + i;
        size_t base = ((size_t)b * Sn + i) * Sn;
        bool hu = false, hd = false;
        float su = 0.f, sd = 0.f;
        float cc = g_c;
        if (i < Sn - 1 && eos[base + i + 1] != 0) {
            hu = true;
            su = (g_dup[r] + g_xu[r] + g_xv[r + 1] + cc) * invD;
        }
        if (i > 0 && eos[base + i - 1] != 0) {
            hd = true;
            sd = (g_ddn[r] + g_xu[r] + g_xv[r - 1] + cc) * invD;
        }
        float up = 0.f, dn = 0.f, dg = 0.f;
        if (!hu && !hd) { up = invS; dn = invS; dg = invS; }
        else if (hu && hd) {
            float m = fmaxf(su, sd);
            float eu = expf(su - m), ed = expf(sd - m);
            float inv = 1.0f / (eu + ed);
            up = eu * inv; dn = ed * inv;
        } else if (hu) up = 1.f;
        else dn = 1.f;
        s_up[i] = up; s_dn[i] = dn;
        g_rvup[r] = up; g_rvdn[r] = dn; g_rvdiag[r] = dg;
        g_fm[r] = (!hu && !hd) ? 1 : 0;
    }
    __syncthreads();

    auto Lval = [&](int i) -> double {    // i in [0, Sn-2]
        float pr = prior[((size_t)b * Sn + i) * Sn + i + 1];
        float p = s_up[i] * s_dn[i + 1];
        float nsym = sqrtf(p + 1e-9f);
        float na = pr + (1.0f - pr) * nsym;
        return (double)logf(na + 1e-9f);
    };

    int j0 = 2 * t, j1 = 2 * t + 1;
    double a = (j0 == 0) ? 0.0 : Lval(j0 - 1);
    double c = Lval(j1 - 1);
    double pair = a + c;
    sh[t] = pair;
    __syncthreads();
    for (int off = 1; off < 1024; off <<= 1) {
        double v = sh[t];
        if (t >= off) v += sh[t - off];
        __syncthreads();
        sh[t] = v;
        __syncthreads();
    }
    double excl = sh[t] - pair;
    g_P[rb + j0] = excl + a;
    g_P[rb + j1] = excl + a + c;
}

// ---------------- dense epilogue: write na and g_attn -----------------------
// Non-band sqrt takes only 2 constant values; exp saturates to 1e-9 past |d|>38.
__global__ void dense_kernel(const float* __restrict__ prior,
                             float* __restrict__ out_g,
                             float* __restrict__ out_na) {
    const float C0 = 3.16227766e-5f;        // sqrtf(1e-9f)
    const float Cm = 4.89304178e-4f;        // sqrtf(invS^2 + 1e-9f), invS=1/2048
    int b  = blockIdx.z;
    int i  = blockIdx.y * 4 + threadIdx.y;
    int j0 = (blockIdx.x * 64 + threadIdx.x) * 4;
    size_t rb  = (size_t)b * Sn;
    size_t off = (rb + i) * Sn + j0;
    float4 pr4 = *(const float4*)(prior + off);
    double Pi = g_P[rb + i];
    double2 p01 = *(const double2*)(g_P + rb + j0);
    double2 p23 = *(const double2*)(g_P + rb + j0 + 2);
    double Pj[4] = {p01.x, p01.y, p23.x, p23.y};
    float na4[4], ga4[4];

    bool near = (j0 <= i + 1) && (j0 + 3 >= i - 1);
    if (!near) {
        unsigned char fmi = g_fm[rb + i];
        uchar4 fmj = *(const uchar4*)(g_fm + rb + j0);
        const unsigned char* fj = (const unsigned char*)&fmj;
        bool right = (j0 > i);
        #pragma unroll
        for (int jj = 0; jj < 4; jj++) {
            float pr = (&pr4.x)[jj];
            float C = (fmi && fj[jj]) ? Cm : C0;
            na4[jj] = pr + (1.0f - pr) * C;
        }
        float dlead = right ? (float)(Pj[0] - Pi) : (float)(Pi - Pj[3]);
        if (dlead <= -38.0f) {
            #pragma unroll
            for (int jj = 0; jj < 4; jj++) ga4[jj] = 1e-9f;
        } else {
            #pragma unroll
            for (int jj = 0; jj < 4; jj++) {
                float d = right ? (float)(Pj[jj] - Pi) : (float)(Pi - Pj[jj]);
                ga4[jj] = (d > -38.0f) ? (__expf(d) + 1e-9f) : 1e-9f;
            }
        }
    } else {
        float di = g_rvdiag[rb + i];
        #pragma unroll
        for (int jj = 0; jj < 4; jj++) {
            int j = j0 + jj;
            float pr = (&pr4.x)[jj];
            float p;
            if      (j == i)     p = di * di;
            else if (j == i + 1) p = g_rvup[rb + i] * g_rvdn[rb + j];
            else if (j == i - 1) p = g_rvdn[rb + i] * g_rvup[rb + j];
            else                 p = di * g_rvdiag[rb + j];
            float na = pr + (1.0f - pr) * sqrtf(p + 1e-9f);
            float ga;
            if (j == i) ga = na;
            else {
                double d = Pj[jj] - Pi;
                if (j < i) d = -d;
                ga = expf((float)d) + 1e-9f;
            }
            na4[jj] = na; ga4[jj] = ga;
        }
    }
    *(float4*)(out_na + off) = make_float4(na4[0], na4[1], na4[2], na4[3]);
    *(float4*)(out_g  + off) = make_float4(ga4[0], ga4[1], ga4[2], ga4[3]);
}

// ---------------- launch ----------------------------------------------------
extern "C" void kernel_launch(void* const* d_in, const int* in_sizes, int n_in,
                              void* d_out, int out_size) {
    const float* ctx   = (const float*)d_in[0];
    const int*   eos   = (const int*)  d_in[1];
    const float* prior = (const float*)d_in[2];
    const float* Wq    = (const float*)d_in[3];
    const float* bq    = (const float*)d_in[4];
    const float* Wk    = (const float*)d_in[5];
    const float* bk    = (const float*)d_in[6];
    const float* gamma = (const float*)d_in[7];
    const float* beta  = (const float*)d_in[8];
    float* out_g  = (float*)d_out;
    float* out_na = out_g + (size_t)Bn * Sn * Sn;

    float *pMp;
    __nv_bfloat16 *pA1, *pB1, *pA2, *pB2, *pYh;
    cudaGetSymbolAddress((void**)&pMp, g_Mp);
    cudaGetSymbolAddress((void**)&pA1, g_A1);
    cudaGetSymbolAddress((void**)&pB1, g_B1);
    cudaGetSymbolAddress((void**)&pA2, g_A2);
    cudaGetSymbolAddress((void**)&pB2, g_B2);
    cudaGetSymbolAddress((void**)&pYh, g_yh);

    const int smem3 = 3 * 2 * 128 * 128;   // 98304 bytes (3 stages x 32KB)
    static int attr_done = 0;
    if (!attr_done) {
        cudaFuncSetAttribute(gemm_mma<false>, cudaFuncAttributeMaxDynamicSharedMemorySize, smem3);
        cudaFuncSetAttribute(gemm_mma<true>,  cudaFuncAttributeMaxDynamicSharedMemorySize, smem3);
        attr_done = 1;
    }

    prep_kernel<<<2 * Dn + 1, 256>>>(Wq, Wk, bq, bk);
    ln_kernel<<<BSn, 256>>>(ctx, gamma, beta);
    // GEMM1 (1-term, split-K x2): partials of M = Wq @ Wk^T into g_Mp
    gemm_mma<false><<<dim3(Dn / 128, Dn / 128, NSPLIT), 128, smem3>>>(pA1, pB1, pMp, nullptr, Dn, (size_t)Dn * Dn, K1TOT / NSPLIT);
    // combine partials -> transposed hi operand B2
    combine_split<<<dim3(Dn / 32, Dn / 32), dim3(32, 8)>>>();
    // GEMM2: y = x @ M  (1-term: xh*Mh, 16 chunks) -> bf16 g_yh
    gemm_mma<true><<<dim3(Dn / 128, BSn / 128, 1), 128, smem3>>>(pA2, pB2, nullptr, pYh, Dn, 0, K2TOT);
    dots_kernel<<<BSn / 2, 256>>>();
    scan_softmax<<<Bn, 1024>>>(eos, prior);
    dense_kernel<<<dim3(Sn / 256, Sn / 4, Bn), dim3(64, 4)>>>(prior, out_g, out_na);
}